// round 14
// baseline (speedup 1.0000x reference)
#include <cuda_runtime.h>
#include <cuda_bf16.h>
#include <cstdint>
#include <cstddef>

// Problem constants
#define BB 512
#define TT 512
#define FF 64
#define PP 32
#define UU 512

// Affine-state formulation
#define ZP   1600
#define HOM  1568
#define CH   32
#define NCH  (TT/CH)
#define XCW  (CH*FF)       // 2048
#define YW   (CH*PP)       // 1024
#define MROW (BB*NCH)      // 8192
#define CW   (YW+ZP)       // 2624
#define PWP  1664          // power-plane pitch (1600 data + pad)

typedef unsigned long long u64;
typedef __nv_bfloat16 bf16;

// ---------------- fp32 scratch ----------------
__device__ __align__(256) float gM[ZP*ZP];
__device__ __align__(256) float gN[64*ZP];
__device__ __align__(256) float gT1[ZP*UU];
__device__ __align__(256) float gT2[64*UU];
__device__ __align__(256) float gY[ZP*PP];            // D seed (1600 x 32)
__device__ __align__(256) float gNY[64*YW];
__device__ __align__(256) float gXC[(size_t)MROW*CW];

// ---------------- bf16 planes ----------------
__device__ __align__(256) bf16 gp0h[(size_t)ZP*PWP], gp0l[(size_t)ZP*PWP];  // power ping
__device__ __align__(256) bf16 gp1h[(size_t)ZP*PWP], gp1l[(size_t)ZP*PWP];  // power pong
__device__ __align__(256) bf16 gvh[(size_t)XCW*ZP],  gvl[(size_t)XCW*ZP];   // V stack (2048 x 1600)
__device__ __align__(256) bf16 gyh[(size_t)ZP*YW],   gyl[(size_t)ZP*YW];    // Y stack (1600 x 1024)
__device__ __align__(256) bf16 ghh[(size_t)XCW*CW],  ghl[(size_t)XCW*CW];   // Hcat planes
__device__ __align__(256) bf16 gxh[(size_t)MROW*XCW], gxl[(size_t)MROW*XCW];
__device__ __align__(256) bf16 gzh[(size_t)MROW*ZP], gzl[(size_t)MROW*ZP];  // chunk-state stack

// ================= PTX helpers =================
__device__ __forceinline__ uint32_t bfpack(float x, float y) {  // lo=x, hi=y
    uint32_t r;
    asm("cvt.rn.bf16x2.f32 %0, %1, %2;" : "=r"(r) : "f"(y), "f"(x));
    return r;
}
__device__ __forceinline__ void ldsm4(uint32_t& r0, uint32_t& r1,
                                      uint32_t& r2, uint32_t& r3, uint32_t a) {
    asm volatile("ldmatrix.sync.aligned.m8n8.x4.shared.b16 {%0,%1,%2,%3}, [%4];"
                 : "=r"(r0), "=r"(r1), "=r"(r2), "=r"(r3) : "r"(a));
}
__device__ __forceinline__ void ldsm4t(uint32_t& r0, uint32_t& r1,
                                       uint32_t& r2, uint32_t& r3, uint32_t a) {
    asm volatile("ldmatrix.sync.aligned.m8n8.x4.trans.shared.b16 {%0,%1,%2,%3}, [%4];"
                 : "=r"(r0), "=r"(r1), "=r"(r2), "=r"(r3) : "r"(a));
}
__device__ __forceinline__ void mma16816(float* c, const uint32_t* a, const uint32_t* b) {
    asm volatile("mma.sync.aligned.m16n8k16.row.col.f32.bf16.bf16.f32 "
                 "{%0,%1,%2,%3}, {%4,%5,%6,%7}, {%8,%9}, {%0,%1,%2,%3};"
                 : "+f"(c[0]), "+f"(c[1]), "+f"(c[2]), "+f"(c[3])
                 : "r"(a[0]), "r"(a[1]), "r"(a[2]), "r"(a[3]),
                   "r"(b[0]), "r"(b[1]));
}
__device__ __forceinline__ void cpa16(uint32_t d, const void* g, int bytes) {
    asm volatile("cp.async.cg.shared.global [%0], [%1], 16, %2;"
                 :: "r"(d), "l"(g), "r"(bytes));
}
__device__ __forceinline__ void cpcommit() { asm volatile("cp.async.commit_group;"); }
template<int n> __device__ __forceinline__ void cpwait() {
    asm volatile("cp.async.wait_group %0;" :: "n"(n));
}

// ================= pre-split bf16 GEMM (plane in / plane+fp32 out) ==========
#define S2   4
#define AROW 80
#define BROW 272
#define A_T  (128*AROW)
#define B_T  (32*BROW)
#define SLOT (2*A_T + 2*B_T)
#define GS2  (S2*SLOT)

__device__ __forceinline__ void issue_stage(
    uint32_t sb, int s, int m0, int n0, int M, int N, int lda, int ldb,
    const bf16* __restrict__ Ah, const bf16* __restrict__ Al,
    const bf16* __restrict__ Bh, const bf16* __restrict__ Bl, int tid)
{
    const int k0 = s * 32;
    const uint32_t sl = sb + (uint32_t)((s % S2) * SLOT);
#pragma unroll
    for (int q = 0; q < 2; ++q) {
        int c = tid + q * 256;
        int m = c >> 2, kc = c & 3;
        int row = m0 + m;
        int bytes = (row < M) ? 16 : 0;
        int rs = bytes ? row : 0;
        const bf16* s1 = Ah + (size_t)rs * lda + k0 + kc * 8;
        const bf16* s2 = Al + (size_t)rs * lda + k0 + kc * 8;
        cpa16(sl + m * AROW + kc * 16, s1, bytes);
        cpa16(sl + A_T + m * AROW + kc * 16, s2, bytes);
    }
#pragma unroll
    for (int q = 0; q < 2; ++q) {
        int c = tid + q * 256;
        int k = c >> 4, nc = c & 15;
        int col = n0 + nc * 8;
        int bytes = (col < N) ? 16 : 0;
        int cs = bytes ? col : 0;
        const bf16* s1 = Bh + (size_t)(k0 + k) * ldb + cs;
        const bf16* s2 = Bl + (size_t)(k0 + k) * ldb + cs;
        cpa16(sl + 2 * A_T + k * BROW + nc * 16, s1, bytes);
        cpa16(sl + 2 * A_T + B_T + k * BROW + nc * 16, s2, bytes);
    }
    cpcommit();
}

__global__ void __launch_bounds__(256, 1) gemm_bf(
    const bf16* __restrict__ Ah, const bf16* __restrict__ Al, int lda,
    const bf16* __restrict__ Bh, const bf16* __restrict__ Bl, int ldb,
    float* __restrict__ C, int ldc, int M, int N, int K, int accum,
    bf16* __restrict__ oh, bf16* __restrict__ ol, int opitch)
{
    extern __shared__ __align__(16) char smem[];
    const uint32_t sb = (uint32_t)__cvta_generic_to_shared(smem);
    const int tid  = threadIdx.x;
    const int wid  = tid >> 5;
    const int lane = tid & 31;
    const int m0 = blockIdx.y * 128;
    const int n0 = blockIdx.x * 128;
    const int wm = (wid >> 2) * 64;
    const int wn = (wid & 3) * 32;

    float acc[4][4][4];
#pragma unroll
    for (int mi = 0; mi < 4; ++mi)
#pragma unroll
        for (int ni = 0; ni < 4; ++ni)
#pragma unroll
            for (int r = 0; r < 4; ++r) acc[mi][ni][r] = 0.f;

    const int nk = K / 32;
    const int pro = (S2 - 1 < nk) ? S2 - 1 : nk;
    for (int s = 0; s < pro; ++s)
        issue_stage(sb, s, m0, n0, M, N, lda, ldb, Ah, Al, Bh, Bl, tid);

    const uint32_t a_lrow = (uint32_t)(lane & 15);
    const uint32_t a_lchk = (uint32_t)(lane >> 4);
    const uint32_t b_krow = (uint32_t)(lane & 15);
    const uint32_t b_ncol = (uint32_t)((lane >> 4) * 8);

    for (int s = 0; s < nk; ++s) {
        cpwait<S2 - 2>();
        __syncthreads();
        if (s + S2 - 1 < nk)
            issue_stage(sb, s + S2 - 1, m0, n0, M, N, lda, ldb, Ah, Al, Bh, Bl, tid);

        const uint32_t base = sb + (uint32_t)((s % S2) * SLOT);
#pragma unroll
        for (int kk = 0; kk < 2; ++kk) {
            uint32_t ah[4][4], al[4][4], bh[4][2], bl[4][2];
#pragma unroll
            for (int mi = 0; mi < 4; ++mi) {
                uint32_t off = (uint32_t)(wm + mi * 16 + a_lrow) * AROW
                             + (uint32_t)(kk * 2 + a_lchk) * 16;
                ldsm4(ah[mi][0], ah[mi][1], ah[mi][2], ah[mi][3], base + off);
                ldsm4(al[mi][0], al[mi][1], al[mi][2], al[mi][3], base + A_T + off);
            }
#pragma unroll
            for (int h = 0; h < 2; ++h) {
                uint32_t off = (uint32_t)(kk * 16 + b_krow) * BROW
                             + (uint32_t)(wn + h * 16 + b_ncol) * 2;
                uint32_t t0, t1, t2, t3;
                ldsm4t(t0, t1, t2, t3, base + 2 * A_T + off);
                bh[2*h][0] = t0; bh[2*h][1] = t1; bh[2*h+1][0] = t2; bh[2*h+1][1] = t3;
                ldsm4t(t0, t1, t2, t3, base + 2 * A_T + B_T + off);
                bl[2*h][0] = t0; bl[2*h][1] = t1; bl[2*h+1][0] = t2; bl[2*h+1][1] = t3;
            }
#pragma unroll
            for (int mi = 0; mi < 4; ++mi)
#pragma unroll
                for (int ni = 0; ni < 4; ++ni) {
                    mma16816(acc[mi][ni], ah[mi], bh[ni]);
                    mma16816(acc[mi][ni], ah[mi], bl[ni]);
                    mma16816(acc[mi][ni], al[mi], bh[ni]);
                }
        }
    }

    // epilogue: optional fp32 C, optional bf16 hi/lo planes
#pragma unroll
    for (int mi = 0; mi < 4; ++mi) {
        int r0 = m0 + wm + mi * 16 + (lane >> 2);
        int r1 = r0 + 8;
#pragma unroll
        for (int ni = 0; ni < 4; ++ni) {
            int cc = n0 + wn + ni * 8 + (lane & 3) * 2;
            if (cc < N) {
#pragma unroll
                for (int hh2 = 0; hh2 < 2; ++hh2) {
                    int row = hh2 ? r1 : r0;
                    if (row < M) {
                        float vx = acc[mi][ni][hh2 * 2];
                        float vy = acc[mi][ni][hh2 * 2 + 1];
                        if (C) {
                            float2* p = reinterpret_cast<float2*>(&C[(size_t)row * ldc + cc]);
                            if (accum) { float2 v = *p; vx += v.x; vy += v.y; }
                            *p = make_float2(vx, vy);
                        }
                        if (oh) {
                            float hx = __bfloat162float(__float2bfloat16(vx));
                            float hy = __bfloat162float(__float2bfloat16(vy));
                            size_t oidx = (size_t)row * opitch + cc;
                            *reinterpret_cast<uint32_t*>(oh + oidx) = bfpack(vx, vy);
                            *reinterpret_cast<uint32_t*>(ol + oidx) = bfpack(vx - hx, vy - hy);
                        }
                    }
                }
            }
        }
    }
}

// ================= slow path: fp32-input GEMM (small builds) ==
#define TBM 128
#define TBN 128
#define TBK 32
#define ROWB 80
#define TILEB (128*ROWB)
#define BUFB (4*TILEB)
#define GSMEM (2*BUFB)

__device__ __forceinline__ void ldg_tiles(
    const float* __restrict__ A, int lda, int M, int m0,
    const float* __restrict__ B, int ldb, int N, int n0,
    int k0, int smr, int kh, float4 ra[4], float rb[16])
{
    const float4 z4 = make_float4(0.f, 0.f, 0.f, 0.f);
    if (m0 + smr < M) {
        const float* ap = A + (size_t)(m0 + smr) * lda + k0 + kh;
#pragma unroll
        for (int j = 0; j < 4; ++j)
            ra[j] = *reinterpret_cast<const float4*>(ap + 4 * j);
    } else {
#pragma unroll
        for (int j = 0; j < 4; ++j) ra[j] = z4;
    }
    if (n0 + smr < N) {
        const float* bp = B + (size_t)(k0 + kh) * ldb + (n0 + smr);
#pragma unroll
        for (int j = 0; j < 16; ++j) rb[j] = bp[(size_t)j * ldb];
    } else {
#pragma unroll
        for (int j = 0; j < 16; ++j) rb[j] = 0.f;
    }
}
__device__ __forceinline__ void split8(const float* v, uint32_t* hw, uint32_t* lw) {
#pragma unroll
    for (int j = 0; j < 8; ++j) {
        float x = v[2 * j], y = v[2 * j + 1];
        float hx = __bfloat162float(__float2bfloat16(x));
        float hy = __bfloat162float(__float2bfloat16(y));
        hw[j] = bfpack(x, y);
        lw[j] = bfpack(x - hx, y - hy);
    }
}
__device__ __forceinline__ void sts_tiles(char* smem, int buf, int smr, int kh,
                                          const float4 ra[4], const float rb[16])
{
    char* base = smem + buf * BUFB;
    uint32_t hw[8], lw[8];
    float av[16];
#pragma unroll
    for (int j = 0; j < 4; ++j) {
        av[4*j] = ra[j].x; av[4*j+1] = ra[j].y; av[4*j+2] = ra[j].z; av[4*j+3] = ra[j].w;
    }
    split8(av, hw, lw);
    {
        char* d = base + smr * ROWB + kh * 2;
        *reinterpret_cast<uint4*>(d)      = make_uint4(hw[0], hw[1], hw[2], hw[3]);
        *reinterpret_cast<uint4*>(d + 16) = make_uint4(hw[4], hw[5], hw[6], hw[7]);
        char* d2 = d + TILEB;
        *reinterpret_cast<uint4*>(d2)      = make_uint4(lw[0], lw[1], lw[2], lw[3]);
        *reinterpret_cast<uint4*>(d2 + 16) = make_uint4(lw[4], lw[5], lw[6], lw[7]);
    }
    split8(rb, hw, lw);
    {
        char* d = base + 2 * TILEB + smr * ROWB + kh * 2;
        *reinterpret_cast<uint4*>(d)      = make_uint4(hw[0], hw[1], hw[2], hw[3]);
        *reinterpret_cast<uint4*>(d + 16) = make_uint4(hw[4], hw[5], hw[6], hw[7]);
        char* d2 = d + TILEB;
        *reinterpret_cast<uint4*>(d2)      = make_uint4(lw[0], lw[1], lw[2], lw[3]);
        *reinterpret_cast<uint4*>(d2 + 16) = make_uint4(lw[4], lw[5], lw[6], lw[7]);
    }
}

__global__ void __launch_bounds__(256, 1) tcgemm_k(
    const float* __restrict__ A, int lda,
    const float* __restrict__ B, int ldb,
    float* __restrict__ C, int ldc,
    int M, int N, int K, int accum)
{
    extern __shared__ __align__(16) char smem[];
    const uint32_t sb = (uint32_t)__cvta_generic_to_shared(smem);
    const int tid  = threadIdx.x;
    const int wid  = tid >> 5;
    const int lane = tid & 31;
    const int m0 = blockIdx.y * TBM;
    const int n0 = blockIdx.x * TBN;
    const int wm = (wid >> 2) * 64;
    const int wn = (wid & 3) * 32;
    const int smr = tid >> 1;
    const int kh  = (tid & 1) * 16;

    float acc[4][4][4];
#pragma unroll
    for (int mi = 0; mi < 4; ++mi)
#pragma unroll
        for (int ni = 0; ni < 4; ++ni)
#pragma unroll
            for (int r = 0; r < 4; ++r) acc[mi][ni][r] = 0.f;

    const uint32_t a_lrow = (uint32_t)(lane & 15);
    const uint32_t a_lchk = (uint32_t)(lane >> 4);
    const uint32_t b_lrow = (uint32_t)(((lane >> 4) << 3) + (lane & 7));
    const uint32_t b_lchk = (uint32_t)((lane >> 3) & 1);

    const int nk = K / TBK;
    float4 ra[4]; float rb[16];
    ldg_tiles(A, lda, M, m0, B, ldb, N, n0, 0, smr, kh, ra, rb);
    sts_tiles(smem, 0, smr, kh, ra, rb);
    __syncthreads();

    for (int s = 0; s < nk; ++s) {
        if (s + 1 < nk)
            ldg_tiles(A, lda, M, m0, B, ldb, N, n0, (s + 1) * TBK, smr, kh, ra, rb);
        const uint32_t base = sb + (uint32_t)((s & 1) * BUFB);
#pragma unroll
        for (int kk = 0; kk < 2; ++kk) {
            uint32_t ah[4][4], al[4][4], bh[4][2], bl[4][2];
#pragma unroll
            for (int mi = 0; mi < 4; ++mi) {
                uint32_t off = (uint32_t)(wm + mi * 16 + a_lrow) * ROWB
                             + (uint32_t)(kk * 2 + a_lchk) * 16;
                ldsm4(ah[mi][0], ah[mi][1], ah[mi][2], ah[mi][3], base + off);
                ldsm4(al[mi][0], al[mi][1], al[mi][2], al[mi][3], base + TILEB + off);
            }
#pragma unroll
            for (int h = 0; h < 2; ++h) {
                uint32_t off = (uint32_t)(wn + h * 16 + b_lrow) * ROWB
                             + (uint32_t)(kk * 2 + b_lchk) * 16;
                uint32_t t0, t1, t2, t3;
                ldsm4(t0, t1, t2, t3, base + 2 * TILEB + off);
                bh[2*h][0] = t0; bh[2*h][1] = t1; bh[2*h+1][0] = t2; bh[2*h+1][1] = t3;
                ldsm4(t0, t1, t2, t3, base + 3 * TILEB + off);
                bl[2*h][0] = t0; bl[2*h][1] = t1; bl[2*h+1][0] = t2; bl[2*h+1][1] = t3;
            }
#pragma unroll
            for (int mi = 0; mi < 4; ++mi)
#pragma unroll
                for (int ni = 0; ni < 4; ++ni) {
                    mma16816(acc[mi][ni], ah[mi], bh[ni]);
                    mma16816(acc[mi][ni], ah[mi], bl[ni]);
                    mma16816(acc[mi][ni], al[mi], bh[ni]);
                }
        }
        __syncthreads();
        if (s + 1 < nk) {
            sts_tiles(smem, (s + 1) & 1, smr, kh, ra, rb);
            __syncthreads();
        }
    }
#pragma unroll
    for (int mi = 0; mi < 4; ++mi) {
        int r0 = m0 + wm + mi * 16 + (lane >> 2);
        int r1 = r0 + 8;
#pragma unroll
        for (int ni = 0; ni < 4; ++ni) {
            int cc = n0 + wn + ni * 8 + (lane & 3) * 2;
            if (cc < N) {
                if (r0 < M) {
                    float2* p = reinterpret_cast<float2*>(&C[(size_t)r0 * ldc + cc]);
                    float2 v = accum ? *p : make_float2(0.f, 0.f);
                    v.x += acc[mi][ni][0]; v.y += acc[mi][ni][1];
                    *p = v;
                }
                if (r1 < M) {
                    float2* p = reinterpret_cast<float2*>(&C[(size_t)r1 * ldc + cc]);
                    float2 v = accum ? *p : make_float2(0.f, 0.f);
                    v.x += acc[mi][ni][2]; v.y += acc[mi][ni][3];
                    *p = v;
                }
            }
        }
    }
}

// ---------------- small helper kernels ----------------
__global__ void kzero(float* p, int n) {
    int i = blockIdx.x * blockDim.x + threadIdx.x;
    if (i < n) p[i] = 0.f;
}
__global__ void kcopy(float* dst, int ldd, const float* src, int lds, int rows, int cols) {
    int i = blockIdx.x * blockDim.x + threadIdx.x;
    if (i >= rows * cols) return;
    int r = i / cols, c = i - r * cols;
    dst[(size_t)r * ldd + c] = src[(size_t)r * lds + c];
}
__global__ void kaddb(float* dst, int ldd, const float* src, int lds, int rows, int cols) {
    int i = blockIdx.x * blockDim.x + threadIdx.x;
    if (i >= rows * cols) return;
    int r = i / cols, c = i - r * cols;
    dst[(size_t)r * ldd + c] += src[(size_t)r * lds + c];
}
__global__ void kvadd2(float* dst, const float* a, const float* b, int n) {
    int i = blockIdx.x * blockDim.x + threadIdx.x;
    if (i < n) dst[i] = a[i] + b[i];
}
__global__ void kvaddrow(float* dst, const float* src, int n) {
    int i = blockIdx.x * blockDim.x + threadIdx.x;
    if (i < n) dst[i] += src[i];
}
__global__ void kdiag(float* M) {
    int i = threadIdx.x;
    if (i < PP) M[(size_t)(1536 + i) * ZP + 1536 + i] += 1.f;
    if (i == PP) M[(size_t)HOM * ZP + HOM] += 1.f;
}
// Hy plane region: rows 0..2047, cols 0..1023 of Hcat planes (split inline)
__global__ void khbuild_bf(bf16* hh, bf16* hl, const float* NY, const float* Nm) {
    int idx = blockIdx.x * blockDim.x + threadIdx.x;
    if (idx >= XCW * YW) return;
    int row = idx >> 10, col = idx & 1023;
    int i = row >> 6, f = row & 63;
    int j = col >> 5, p = col & 31;
    float v = 0.f;
    if (j == i)      v = Nm[(size_t)f * ZP + 1536 + p];
    else if (j > i)  v = NY[(size_t)f * YW + (j - i - 1) * PP + p];
    bf16 h = __float2bfloat16(v);
    hh[(size_t)row * CW + col] = h;
    hl[(size_t)row * CW + col] = __float2bfloat16(v - __bfloat162float(h));
}
// Q plane region: block-reversed V planes (pure bf16 permutation)
__global__ void kqrev_bf(bf16* hh, bf16* hl, const bf16* vh, const bf16* vl) {
    int idx = blockIdx.x * blockDim.x + threadIdx.x;
    if (idx >= XCW * ZP) return;
    int row = idx / ZP, col = idx - row * ZP;
    int i = row >> 6, f = row & 63;
    size_t src = (size_t)((31 - i) * 64 + f) * ZP + col;
    hh[(size_t)row * CW + YW + col] = vh[src];
    hl[(size_t)row * CW + YW + col] = vl[src];
}
__global__ void kout(float* out, const float* XC) {
    int i = blockIdx.x * blockDim.x + threadIdx.x;
    if (i >= BB * TT * PP) return;
    int b = i / (TT * PP), r = i - b * (TT * PP);
    int t = r >> 5, p = r & 31;
    int c = t >> 5, j = t & 31;
    out[i] = XC[((size_t)b * NCH + c) * CW + j * PP + p];
}
// strided fp32 -> strided bf16 hi/lo planes
__global__ void ksplitP(const float* __restrict__ src, int lds,
                        bf16* __restrict__ hi, bf16* __restrict__ lo, int ldd,
                        int rows, int cols) {
    int i = blockIdx.x * blockDim.x + threadIdx.x;
    if (i >= rows * cols) return;
    int r = i / cols, c = i - r * cols;
    float v = src[(size_t)r * lds + c];
    bf16 h = __float2bfloat16(v);
    hi[(size_t)r * ldd + c] = h;
    lo[(size_t)r * ldd + c] = __float2bfloat16(v - __bfloat162float(h));
}
// z_0 planes into stack rows (b*NCH + 0)
__global__ void kzplanes(bf16* h, bf16* l) {
    int i = blockIdx.x * blockDim.x + threadIdx.x;
    if (i >= BB * ZP) return;
    int b = i / ZP, c = i - b * ZP;
    size_t a = (size_t)(b * NCH) * ZP + c;
    h[a] = __float2bfloat16((c == HOM) ? 1.f : 0.f);
    l[a] = __float2bfloat16(0.f);
}

// ---------------- host ----------------
static void gemm(const float* A, int lda, const float* B, int ldb,
                 float* C, int ldc, int M, int N, int K, int acc)
{
    dim3 g((unsigned)((N + TBN - 1) / TBN), (unsigned)((M + TBM - 1) / TBM));
    tcgemm_k<<<g, 256, GSMEM>>>(A, lda, B, ldb, C, ldc, M, N, K, acc);
}
static void gemmF(const bf16* Ah, const bf16* Al, int lda,
                  const bf16* Bh, const bf16* Bl, int ldb,
                  float* C, int ldc, int M, int N, int K, int acc,
                  bf16* oh = nullptr, bf16* ol = nullptr, int opitch = 0)
{
    dim3 g((unsigned)((N + 127) / 128), (unsigned)((M + 127) / 128));
    gemm_bf<<<g, 256, GS2>>>(Ah, Al, lda, Bh, Bl, ldb, C, ldc, M, N, K, acc,
                             oh, ol, opitch);
}
#define L1D(n) (((n) + 255) / 256), 256
static void splitP(const float* src, int lds, bf16* hi, bf16* lo, int ldd,
                   int rows, int cols) {
    ksplitP<<<L1D(rows * cols)>>>(src, lds, hi, lo, ldd, rows, cols);
}

extern "C" void kernel_launch(void* const* d_in, const int* in_sizes, int n_in,
                              void* d_out, int out_size)
{
    const float* x    = (const float*)d_in[0];
    const float* WA   = (const float*)d_in[1];
    const float* bA   = (const float*)d_in[2];
    const float* WB0  = (const float*)d_in[3];
    const float* bB0  = (const float*)d_in[4];
    const float* WBr  = (const float*)d_in[5];
    const float* bBr  = (const float*)d_in[6];
    const float* WC   = (const float*)d_in[7];
    const float* bC   = (const float*)d_in[8];
    const float* Wout = (const float*)d_in[9];
    const float* bout = (const float*)d_in[10];
    float* out = (float*)d_out;

    static int attr_done = 0;
    if (!attr_done) {
        cudaFuncSetAttribute(tcgemm_k, cudaFuncAttributeMaxDynamicSharedMemorySize, GSMEM);
        cudaFuncSetAttribute(gemm_bf,  cudaFuncAttributeMaxDynamicSharedMemorySize, GS2);
        attr_done = 1;
    }

    float *M_, *N_, *T1_, *T2_, *Y_, *NY_, *XC_;
    cudaGetSymbolAddress((void**)&M_,  gM);   cudaGetSymbolAddress((void**)&N_,  gN);
    cudaGetSymbolAddress((void**)&T1_, gT1);  cudaGetSymbolAddress((void**)&T2_, gT2);
    cudaGetSymbolAddress((void**)&Y_,  gY);   cudaGetSymbolAddress((void**)&NY_, gNY);
    cudaGetSymbolAddress((void**)&XC_, gXC);

    bf16 *p0h, *p0l, *p1h, *p1l, *vh, *vl, *yh, *yl, *hh, *hl, *xh, *xl, *zh, *zl;
    cudaGetSymbolAddress((void**)&p0h, gp0h); cudaGetSymbolAddress((void**)&p0l, gp0l);
    cudaGetSymbolAddress((void**)&p1h, gp1h); cudaGetSymbolAddress((void**)&p1l, gp1l);
    cudaGetSymbolAddress((void**)&vh,  gvh);  cudaGetSymbolAddress((void**)&vl,  gvl);
    cudaGetSymbolAddress((void**)&yh,  gyh);  cudaGetSymbolAddress((void**)&yl,  gyl);
    cudaGetSymbolAddress((void**)&hh,  ghh);  cudaGetSymbolAddress((void**)&hl,  ghl);
    cudaGetSymbolAddress((void**)&xh,  gxh);  cudaGetSymbolAddress((void**)&xl,  gxl);
    cudaGetSymbolAddress((void**)&zh,  gzh);  cudaGetSymbolAddress((void**)&zl,  gzl);

    const int W2 = UU * UU;

    // ---- build M (step matrix) and N (input matrix) — fp32 slow path ----
    kzero<<<L1D(ZP*ZP)>>>(M_, ZP*ZP);
    kzero<<<L1D(64*ZP)>>>(N_, 64*ZP);

    kcopy<<<L1D(UU*UU)>>>(M_,                   ZP, WA,          UU, UU, UU);
    kcopy<<<L1D(PP*UU)>>>(M_ + (size_t)1536*ZP, ZP, WB0 + 64*UU, UU, PP, UU);
    kvadd2<<<L1D(UU)>>>(M_ + (size_t)HOM*ZP, bA, bB0, UU);
    kcopy<<<L1D(64*UU)>>>(N_,                   ZP, WB0,         UU, 64, UU);

    gemm(M_, ZP, WC, UU, T1_, UU, ZP, UU, UU, 0);
    kvaddrow<<<L1D(UU)>>>(T1_ + (size_t)HOM*UU, bC, UU);
    gemm(T1_, UU, WBr, UU, M_ + 512, ZP, ZP, UU, UU, 0);
    kaddb<<<L1D(UU*UU)>>>(M_ + (size_t)512*ZP + 512, ZP, WA + W2, UU, UU, UU);
    kvaddrow<<<L1D(UU)>>>(M_ + (size_t)HOM*ZP + 512, bA + UU, UU);
    kvaddrow<<<L1D(UU)>>>(M_ + (size_t)HOM*ZP + 512, bBr, UU);
    gemm(N_, ZP, WC, UU, T2_, UU, 64, UU, UU, 0);
    gemm(T2_, UU, WBr, UU, N_ + 512, ZP, 64, UU, UU, 0);

    gemm(M_ + 512, ZP, WC + W2, UU, T1_, UU, ZP, UU, UU, 0);
    kvaddrow<<<L1D(UU)>>>(T1_ + (size_t)HOM*UU, bC + UU, UU);
    gemm(T1_, UU, WBr + W2, UU, M_ + 1024, ZP, ZP, UU, UU, 0);
    kaddb<<<L1D(UU*UU)>>>(M_ + (size_t)1024*ZP + 1024, ZP, WA + 2*W2, UU, UU, UU);
    kvaddrow<<<L1D(UU)>>>(M_ + (size_t)HOM*ZP + 1024, bA + 2*UU, UU);
    kvaddrow<<<L1D(UU)>>>(M_ + (size_t)HOM*ZP + 1024, bBr + UU, UU);
    gemm(N_ + 512, ZP, WC + W2, UU, T2_, UU, 64, UU, UU, 0);
    gemm(T2_, UU, WBr + W2, UU, N_ + 1024, ZP, 64, UU, UU, 0);

    gemm(M_ + 1024, ZP, WC + 2*W2, UU, T1_, UU, ZP, UU, UU, 0);
    kvaddrow<<<L1D(UU)>>>(T1_ + (size_t)HOM*UU, bC + 2*UU, UU);
    gemm(T1_, UU, Wout, PP, M_ + 1536, ZP, ZP, PP, UU, 0);
    kvaddrow<<<L1D(PP)>>>(M_ + (size_t)HOM*ZP + 1536, bout, PP);
    kcopy<<<L1D(ZP*PP)>>>(Y_, PP, M_ + 1536, ZP, ZP, PP);   // D seed (pre-identity)
    kdiag<<<1, 64>>>(M_);
    gemm(N_ + 1024, ZP, WC + 2*W2, UU, T2_, UU, 64, UU, UU, 0);
    gemm(T2_, UU, Wout, PP, N_ + 1536, ZP, 64, PP, UU, 0);

    // x split can go early (independent)
    splitP(x, XCW, xh, xl, XCW, MROW, XCW);

    // ---- seed planes ----
    splitP(M_, ZP, p0h, p0l, PWP, ZP, ZP);     // power = M
    splitP(N_, ZP, vh, vl, ZP, 64, ZP);        // V_0 = N
    splitP(Y_, PP, yh, yl, YW, ZP, PP);        // Ystack block 0 = D

    // ---- doubling rounds: 3 plane-GEMMs each, no helpers between ----
    bf16 *pch = p0h, *pcl = p0l, *pnh = p1h, *pnl = p1l;
    for (int d = 0; d < 5; ++d) {
        const int w = 32 << d, r = 64 << d;
        // Y append: M^{2^d} * Y[:,0:w] -> Y[:,w:2w]
        gemmF(pch, pcl, PWP, yh, yl, YW, nullptr, 0, ZP, w, ZP, 0,
              yh + w, yl + w, YW);
        // V append: V[0:r,:] * M^{2^d} -> V[r:2r,:]
        gemmF(vh, vl, ZP, pch, pcl, PWP, nullptr, 0, r, ZP, ZP, 0,
              vh + (size_t)r * ZP, vl + (size_t)r * ZP, ZP);
        // power square -> other buffer
        gemmF(pch, pcl, PWP, pch, pcl, PWP, nullptr, 0, ZP, ZP, ZP, 0,
              pnh, pnl, PWP);
        bf16* t;
        t = pch; pch = pnh; pnh = t;
        t = pcl; pcl = pnl; pnl = t;
    }
    // pch/pcl now hold M^32 planes

    // ---- NY = N * Ystack (planes) ; Hcat planes directly ----
    gemmF(vh, vl, ZP, yh, yl, YW, NY_, YW, 64, YW, ZP, 0);
    khbuild_bf<<<L1D(XCW*YW)>>>(hh, hl, NY_, N_);
    kqrev_bf<<<L1D(XCW*ZP)>>>(hh, hl, vh, vl);

    // ---- giant x-driven GEMM: XC = X * Hcat (8192 x 2624 x 2048) ----
    gemmF(xh, xl, XCW, hh, hl, CW, XC_, CW, MROW, CW, XCW, 0);

    // ---- serial z-chain (N=1600 only), states in dense (b,c) stack ----
    kzplanes<<<L1D(BB*ZP)>>>(zh, zl);
    for (int c = 0; c < NCH; ++c) {
        bf16* oh = (c < NCH - 1) ? (zh + (size_t)(c + 1) * ZP) : nullptr;
        bf16* ol = (c < NCH - 1) ? (zl + (size_t)(c + 1) * ZP) : nullptr;
        gemmF(zh + (size_t)c * ZP, zl + (size_t)c * ZP, NCH * ZP,
              pch, pcl, PWP,
              XC_ + (size_t)c * CW + YW, NCH * CW,
              BB, ZP, ZP, 1, oh, ol, NCH * ZP);
    }

    // ---- batched y contribution: XC[:, 0:YW] += Zall * Ystack ----
    gemmF(zh, zl, ZP, yh, yl, YW, XC_, CW, MROW, YW, ZP, 1);

    // ---- scatter y-part to output ----
    kout<<<L1D(BB*TT*PP)>>>(out, XC_);
}

// round 15
// speedup vs baseline: 1.2604x; 1.2604x over previous
#include <cuda_runtime.h>
#include <cuda_bf16.h>
#include <cstdint>
#include <cstddef>

// Problem constants
#define BB 512
#define TT 512
#define FF 64
#define PP 32
#define UU 512

// Affine-state formulation
#define ZP   1600
#define HOM  1568
#define CH   32
#define NCH  (TT/CH)
#define XCW  (CH*FF)       // 2048
#define YW   (CH*PP)       // 1024
#define MROW (BB*NCH)      // 8192
#define CW   (YW+ZP)       // 2624
#define AK   1600          // A-plane pitch
#define ARR  3648          // A-plane rows (1600 power + 2048 V stack)

typedef unsigned long long u64;
typedef __nv_bfloat16 bf16;

// ---------------- fp32 scratch ----------------
__device__ __align__(256) float gM[ZP*ZP];
__device__ __align__(256) float gN[64*ZP];
__device__ __align__(256) float gT1[ZP*UU];
__device__ __align__(256) float gT2[64*UU];
__device__ __align__(256) float gY[ZP*PP];
__device__ __align__(256) float gNY[64*YW];
__device__ __align__(256) float gXC[(size_t)MROW*CW];

// ---------------- bf16 planes ----------------
__device__ __align__(256) bf16 gAh[(size_t)ARR*AK], gAl[(size_t)ARR*AK];   // [power; V stack]
__device__ __align__(256) bf16 gBh[(size_t)ZP*CW],  gBl[(size_t)ZP*CW];    // [power | Y stack]
__device__ __align__(256) bf16 gCRh[(size_t)2624*CW], gCRl[(size_t)2624*CW]; // round output
__device__ __align__(256) bf16 gWh[(size_t)ZP*CW],  gWl[(size_t)ZP*CW];    // chain B = [Y | M32]
__device__ __align__(256) bf16 ghh[(size_t)XCW*CW], ghl[(size_t)XCW*CW];   // Hcat planes
__device__ __align__(256) bf16 gxh[(size_t)MROW*XCW], gxl[(size_t)MROW*XCW];
__device__ __align__(256) bf16 gz0h[BB*ZP], gz0l[BB*ZP], gz1h[BB*ZP], gz1l[BB*ZP];

// ================= PTX helpers =================
__device__ __forceinline__ uint32_t bfpack(float x, float y) {  // lo=x, hi=y
    uint32_t r;
    asm("cvt.rn.bf16x2.f32 %0, %1, %2;" : "=r"(r) : "f"(y), "f"(x));
    return r;
}
__device__ __forceinline__ void ldsm4(uint32_t& r0, uint32_t& r1,
                                      uint32_t& r2, uint32_t& r3, uint32_t a) {
    asm volatile("ldmatrix.sync.aligned.m8n8.x4.shared.b16 {%0,%1,%2,%3}, [%4];"
                 : "=r"(r0), "=r"(r1), "=r"(r2), "=r"(r3) : "r"(a));
}
__device__ __forceinline__ void ldsm4t(uint32_t& r0, uint32_t& r1,
                                       uint32_t& r2, uint32_t& r3, uint32_t a) {
    asm volatile("ldmatrix.sync.aligned.m8n8.x4.trans.shared.b16 {%0,%1,%2,%3}, [%4];"
                 : "=r"(r0), "=r"(r1), "=r"(r2), "=r"(r3) : "r"(a));
}
__device__ __forceinline__ void mma16816(float* c, const uint32_t* a, const uint32_t* b) {
    asm volatile("mma.sync.aligned.m16n8k16.row.col.f32.bf16.bf16.f32 "
                 "{%0,%1,%2,%3}, {%4,%5,%6,%7}, {%8,%9}, {%0,%1,%2,%3};"
                 : "+f"(c[0]), "+f"(c[1]), "+f"(c[2]), "+f"(c[3])
                 : "r"(a[0]), "r"(a[1]), "r"(a[2]), "r"(a[3]),
                   "r"(b[0]), "r"(b[1]));
}
__device__ __forceinline__ void cpa16(uint32_t d, const void* g, int bytes) {
    asm volatile("cp.async.cg.shared.global [%0], [%1], 16, %2;"
                 :: "r"(d), "l"(g), "r"(bytes));
}
__device__ __forceinline__ void cpcommit() { asm volatile("cp.async.commit_group;"); }
template<int n> __device__ __forceinline__ void cpwait() {
    asm volatile("cp.async.wait_group %0;" :: "n"(n));
}

// ================= pre-split bf16 GEMM =================
#define S2   4
#define AROW 80
#define BROW 272
#define A_T  (128*AROW)
#define B_T  (32*BROW)
#define SLOT (2*A_T + 2*B_T)
#define GS2  (S2*SLOT)

__device__ __forceinline__ void issue_stage(
    uint32_t sb, int s, int m0, int n0, int M, int N, int lda, int ldb,
    const bf16* __restrict__ Ah, const bf16* __restrict__ Al,
    const bf16* __restrict__ Bh, const bf16* __restrict__ Bl, int tid)
{
    const int k0 = s * 32;
    const uint32_t sl = sb + (uint32_t)((s % S2) * SLOT);
#pragma unroll
    for (int q = 0; q < 2; ++q) {
        int c = tid + q * 256;
        int m = c >> 2, kc = c & 3;
        int row = m0 + m;
        int bytes = (row < M) ? 16 : 0;
        int rs = bytes ? row : 0;
        const bf16* s1 = Ah + (size_t)rs * lda + k0 + kc * 8;
        const bf16* s2 = Al + (size_t)rs * lda + k0 + kc * 8;
        cpa16(sl + m * AROW + kc * 16, s1, bytes);
        cpa16(sl + A_T + m * AROW + kc * 16, s2, bytes);
    }
#pragma unroll
    for (int q = 0; q < 2; ++q) {
        int c = tid + q * 256;
        int k = c >> 4, nc = c & 15;
        int col = n0 + nc * 8;
        int bytes = (col < N) ? 16 : 0;
        int cs = bytes ? col : 0;
        const bf16* s1 = Bh + (size_t)(k0 + k) * ldb + cs;
        const bf16* s2 = Bl + (size_t)(k0 + k) * ldb + cs;
        cpa16(sl + 2 * A_T + k * BROW + nc * 16, s1, bytes);
        cpa16(sl + 2 * A_T + B_T + k * BROW + nc * 16, s2, bytes);
    }
    cpcommit();
}

// C (fp32, optional) and/or bf16 hi/lo plane output (cols >= ocol0, shifted).
__global__ void __launch_bounds__(256, 1) gemm_bf(
    const bf16* __restrict__ Ah, const bf16* __restrict__ Al, int lda,
    const bf16* __restrict__ Bh, const bf16* __restrict__ Bl, int ldb,
    float* __restrict__ C, int ldc, int M, int N, int K, int accum,
    bf16* __restrict__ oh, bf16* __restrict__ ol, int opitch, int ocol0)
{
    extern __shared__ __align__(16) char smem[];
    const uint32_t sb = (uint32_t)__cvta_generic_to_shared(smem);
    const int tid  = threadIdx.x;
    const int wid  = tid >> 5;
    const int lane = tid & 31;
    const int m0 = blockIdx.y * 128;
    const int n0 = blockIdx.x * 128;
    const int wm = (wid >> 2) * 64;
    const int wn = (wid & 3) * 32;

    float acc[4][4][4];
#pragma unroll
    for (int mi = 0; mi < 4; ++mi)
#pragma unroll
        for (int ni = 0; ni < 4; ++ni)
#pragma unroll
            for (int r = 0; r < 4; ++r) acc[mi][ni][r] = 0.f;

    const int nk = K / 32;
    const int pro = (S2 - 1 < nk) ? S2 - 1 : nk;
    for (int s = 0; s < pro; ++s)
        issue_stage(sb, s, m0, n0, M, N, lda, ldb, Ah, Al, Bh, Bl, tid);

    const uint32_t a_lrow = (uint32_t)(lane & 15);
    const uint32_t a_lchk = (uint32_t)(lane >> 4);
    const uint32_t b_krow = (uint32_t)(lane & 15);
    const uint32_t b_ncol = (uint32_t)((lane >> 4) * 8);

    for (int s = 0; s < nk; ++s) {
        cpwait<S2 - 2>();
        __syncthreads();
        if (s + S2 - 1 < nk)
            issue_stage(sb, s + S2 - 1, m0, n0, M, N, lda, ldb, Ah, Al, Bh, Bl, tid);

        const uint32_t base = sb + (uint32_t)((s % S2) * SLOT);
#pragma unroll
        for (int kk = 0; kk < 2; ++kk) {
            uint32_t ah[4][4], al[4][4], bh[4][2], bl[4][2];
#pragma unroll
            for (int mi = 0; mi < 4; ++mi) {
                uint32_t off = (uint32_t)(wm + mi * 16 + a_lrow) * AROW
                             + (uint32_t)(kk * 2 + a_lchk) * 16;
                ldsm4(ah[mi][0], ah[mi][1], ah[mi][2], ah[mi][3], base + off);
                ldsm4(al[mi][0], al[mi][1], al[mi][2], al[mi][3], base + A_T + off);
            }
#pragma unroll
            for (int h = 0; h < 2; ++h) {
                uint32_t off = (uint32_t)(kk * 16 + b_krow) * BROW
                             + (uint32_t)(wn + h * 16 + b_ncol) * 2;
                uint32_t t0, t1, t2, t3;
                ldsm4t(t0, t1, t2, t3, base + 2 * A_T + off);
                bh[2*h][0] = t0; bh[2*h][1] = t1; bh[2*h+1][0] = t2; bh[2*h+1][1] = t3;
                ldsm4t(t0, t1, t2, t3, base + 2 * A_T + B_T + off);
                bl[2*h][0] = t0; bl[2*h][1] = t1; bl[2*h+1][0] = t2; bl[2*h+1][1] = t3;
            }
#pragma unroll
            for (int mi = 0; mi < 4; ++mi)
#pragma unroll
                for (int ni = 0; ni < 4; ++ni) {
                    mma16816(acc[mi][ni], ah[mi], bh[ni]);
                    mma16816(acc[mi][ni], ah[mi], bl[ni]);
                    mma16816(acc[mi][ni], al[mi], bh[ni]);
                }
        }
    }

#pragma unroll
    for (int mi = 0; mi < 4; ++mi) {
        int r0 = m0 + wm + mi * 16 + (lane >> 2);
        int r1 = r0 + 8;
#pragma unroll
        for (int ni = 0; ni < 4; ++ni) {
            int cc = n0 + wn + ni * 8 + (lane & 3) * 2;
            if (cc < N) {
#pragma unroll
                for (int hh2 = 0; hh2 < 2; ++hh2) {
                    int row = hh2 ? r1 : r0;
                    if (row < M) {
                        float vx = acc[mi][ni][hh2 * 2];
                        float vy = acc[mi][ni][hh2 * 2 + 1];
                        if (C) {
                            float2* p = reinterpret_cast<float2*>(&C[(size_t)row * ldc + cc]);
                            if (accum) { float2 v = *p; vx += v.x; vy += v.y; }
                            *p = make_float2(vx, vy);
                        }
                        if (oh && cc >= ocol0) {
                            float hx = __bfloat162float(__float2bfloat16(vx));
                            float hy = __bfloat162float(__float2bfloat16(vy));
                            size_t oidx = (size_t)row * opitch + (cc - ocol0);
                            *reinterpret_cast<uint32_t*>(oh + oidx) = bfpack(vx, vy);
                            *reinterpret_cast<uint32_t*>(ol + oidx) = bfpack(vx - hx, vy - hy);
                        }
                    }
                }
            }
        }
    }
}

// ================= slow path: fp32-input GEMM (small builds) ==
#define TBM 128
#define TBN 128
#define TBK 32
#define ROWB 80
#define TILEB (128*ROWB)
#define BUFB (4*TILEB)
#define GSMEM (2*BUFB)

__device__ __forceinline__ void ldg_tiles(
    const float* __restrict__ A, int lda, int M, int m0,
    const float* __restrict__ B, int ldb, int N, int n0,
    int k0, int smr, int kh, float4 ra[4], float rb[16])
{
    const float4 z4 = make_float4(0.f, 0.f, 0.f, 0.f);
    if (m0 + smr < M) {
        const float* ap = A + (size_t)(m0 + smr) * lda + k0 + kh;
#pragma unroll
        for (int j = 0; j < 4; ++j)
            ra[j] = *reinterpret_cast<const float4*>(ap + 4 * j);
    } else {
#pragma unroll
        for (int j = 0; j < 4; ++j) ra[j] = z4;
    }
    if (n0 + smr < N) {
        const float* bp = B + (size_t)(k0 + kh) * ldb + (n0 + smr);
#pragma unroll
        for (int j = 0; j < 16; ++j) rb[j] = bp[(size_t)j * ldb];
    } else {
#pragma unroll
        for (int j = 0; j < 16; ++j) rb[j] = 0.f;
    }
}
__device__ __forceinline__ void split8(const float* v, uint32_t* hw, uint32_t* lw) {
#pragma unroll
    for (int j = 0; j < 8; ++j) {
        float x = v[2 * j], y = v[2 * j + 1];
        float hx = __bfloat162float(__float2bfloat16(x));
        float hy = __bfloat162float(__float2bfloat16(y));
        hw[j] = bfpack(x, y);
        lw[j] = bfpack(x - hx, y - hy);
    }
}
__device__ __forceinline__ void sts_tiles(char* smem, int buf, int smr, int kh,
                                          const float4 ra[4], const float rb[16])
{
    char* base = smem + buf * BUFB;
    uint32_t hw[8], lw[8];
    float av[16];
#pragma unroll
    for (int j = 0; j < 4; ++j) {
        av[4*j] = ra[j].x; av[4*j+1] = ra[j].y; av[4*j+2] = ra[j].z; av[4*j+3] = ra[j].w;
    }
    split8(av, hw, lw);
    {
        char* d = base + smr * ROWB + kh * 2;
        *reinterpret_cast<uint4*>(d)      = make_uint4(hw[0], hw[1], hw[2], hw[3]);
        *reinterpret_cast<uint4*>(d + 16) = make_uint4(hw[4], hw[5], hw[6], hw[7]);
        char* d2 = d + TILEB;
        *reinterpret_cast<uint4*>(d2)      = make_uint4(lw[0], lw[1], lw[2], lw[3]);
        *reinterpret_cast<uint4*>(d2 + 16) = make_uint4(lw[4], lw[5], lw[6], lw[7]);
    }
    split8(rb, hw, lw);
    {
        char* d = base + 2 * TILEB + smr * ROWB + kh * 2;
        *reinterpret_cast<uint4*>(d)      = make_uint4(hw[0], hw[1], hw[2], hw[3]);
        *reinterpret_cast<uint4*>(d + 16) = make_uint4(hw[4], hw[5], hw[6], hw[7]);
        char* d2 = d + TILEB;
        *reinterpret_cast<uint4*>(d2)      = make_uint4(lw[0], lw[1], lw[2], lw[3]);
        *reinterpret_cast<uint4*>(d2 + 16) = make_uint4(lw[4], lw[5], lw[6], lw[7]);
    }
}

__global__ void __launch_bounds__(256, 1) tcgemm_k(
    const float* __restrict__ A, int lda,
    const float* __restrict__ B, int ldb,
    float* __restrict__ C, int ldc,
    int M, int N, int K, int accum)
{
    extern __shared__ __align__(16) char smem[];
    const uint32_t sb = (uint32_t)__cvta_generic_to_shared(smem);
    const int tid  = threadIdx.x;
    const int wid  = tid >> 5;
    const int lane = tid & 31;
    const int m0 = blockIdx.y * TBM;
    const int n0 = blockIdx.x * TBN;
    const int wm = (wid >> 2) * 64;
    const int wn = (wid & 3) * 32;
    const int smr = tid >> 1;
    const int kh  = (tid & 1) * 16;

    float acc[4][4][4];
#pragma unroll
    for (int mi = 0; mi < 4; ++mi)
#pragma unroll
        for (int ni = 0; ni < 4; ++ni)
#pragma unroll
            for (int r = 0; r < 4; ++r) acc[mi][ni][r] = 0.f;

    const uint32_t a_lrow = (uint32_t)(lane & 15);
    const uint32_t a_lchk = (uint32_t)(lane >> 4);
    const uint32_t b_lrow = (uint32_t)(((lane >> 4) << 3) + (lane & 7));
    const uint32_t b_lchk = (uint32_t)((lane >> 3) & 1);

    const int nk = K / TBK;
    float4 ra[4]; float rb[16];
    ldg_tiles(A, lda, M, m0, B, ldb, N, n0, 0, smr, kh, ra, rb);
    sts_tiles(smem, 0, smr, kh, ra, rb);
    __syncthreads();

    for (int s = 0; s < nk; ++s) {
        if (s + 1 < nk)
            ldg_tiles(A, lda, M, m0, B, ldb, N, n0, (s + 1) * TBK, smr, kh, ra, rb);
        const uint32_t base = sb + (uint32_t)((s & 1) * BUFB);
#pragma unroll
        for (int kk = 0; kk < 2; ++kk) {
            uint32_t ah[4][4], al[4][4], bh[4][2], bl[4][2];
#pragma unroll
            for (int mi = 0; mi < 4; ++mi) {
                uint32_t off = (uint32_t)(wm + mi * 16 + a_lrow) * ROWB
                             + (uint32_t)(kk * 2 + a_lchk) * 16;
                ldsm4(ah[mi][0], ah[mi][1], ah[mi][2], ah[mi][3], base + off);
                ldsm4(al[mi][0], al[mi][1], al[mi][2], al[mi][3], base + TILEB + off);
            }
#pragma unroll
            for (int h = 0; h < 2; ++h) {
                uint32_t off = (uint32_t)(wn + h * 16 + b_lrow) * ROWB
                             + (uint32_t)(kk * 2 + b_lchk) * 16;
                uint32_t t0, t1, t2, t3;
                ldsm4(t0, t1, t2, t3, base + 2 * TILEB + off);
                bh[2*h][0] = t0; bh[2*h][1] = t1; bh[2*h+1][0] = t2; bh[2*h+1][1] = t3;
                ldsm4(t0, t1, t2, t3, base + 3 * TILEB + off);
                bl[2*h][0] = t0; bl[2*h][1] = t1; bl[2*h+1][0] = t2; bl[2*h+1][1] = t3;
            }
#pragma unroll
            for (int mi = 0; mi < 4; ++mi)
#pragma unroll
                for (int ni = 0; ni < 4; ++ni) {
                    mma16816(acc[mi][ni], ah[mi], bh[ni]);
                    mma16816(acc[mi][ni], ah[mi], bl[ni]);
                    mma16816(acc[mi][ni], al[mi], bh[ni]);
                }
        }
        __syncthreads();
        if (s + 1 < nk) {
            sts_tiles(smem, (s + 1) & 1, smr, kh, ra, rb);
            __syncthreads();
        }
    }
#pragma unroll
    for (int mi = 0; mi < 4; ++mi) {
        int r0 = m0 + wm + mi * 16 + (lane >> 2);
        int r1 = r0 + 8;
#pragma unroll
        for (int ni = 0; ni < 4; ++ni) {
            int cc = n0 + wn + ni * 8 + (lane & 3) * 2;
            if (cc < N) {
                if (r0 < M) {
                    float2* p = reinterpret_cast<float2*>(&C[(size_t)r0 * ldc + cc]);
                    float2 v = accum ? *p : make_float2(0.f, 0.f);
                    v.x += acc[mi][ni][0]; v.y += acc[mi][ni][1];
                    *p = v;
                }
                if (r1 < M) {
                    float2* p = reinterpret_cast<float2*>(&C[(size_t)r1 * ldc + cc]);
                    float2 v = accum ? *p : make_float2(0.f, 0.f);
                    v.x += acc[mi][ni][2]; v.y += acc[mi][ni][3];
                    *p = v;
                }
            }
        }
    }
}

// ---------------- small helper kernels ----------------
__global__ void kzero(float* p, int n) {
    int i = blockIdx.x * blockDim.x + threadIdx.x;
    if (i < n) p[i] = 0.f;
}
__global__ void kcopy(float* dst, int ldd, const float* src, int lds, int rows, int cols) {
    int i = blockIdx.x * blockDim.x + threadIdx.x;
    if (i >= rows * cols) return;
    int r = i / cols, c = i - r * cols;
    dst[(size_t)r * ldd + c] = src[(size_t)r * lds + c];
}
__global__ void kaddb(float* dst, int ldd, const float* src, int lds, int rows, int cols) {
    int i = blockIdx.x * blockDim.x + threadIdx.x;
    if (i >= rows * cols) return;
    int r = i / cols, c = i - r * cols;
    dst[(size_t)r * ldd + c] += src[(size_t)r * lds + c];
}
__global__ void kvadd2(float* dst, const float* a, const float* b, int n) {
    int i = blockIdx.x * blockDim.x + threadIdx.x;
    if (i < n) dst[i] = a[i] + b[i];
}
__global__ void kvaddrow(float* dst, const float* src, int n) {
    int i = blockIdx.x * blockDim.x + threadIdx.x;
    if (i < n) dst[i] += src[i];
}
__global__ void kdiag(float* M) {
    int i = threadIdx.x;
    if (i < PP) M[(size_t)(1536 + i) * ZP + 1536 + i] += 1.f;
    if (i == PP) M[(size_t)HOM * ZP + HOM] += 1.f;
}
// Redistribute round output planes: power -> A & B, V append -> A, Y append -> B
__global__ void kround(const bf16* __restrict__ crh, const bf16* __restrict__ crl,
                       bf16* __restrict__ ah, bf16* __restrict__ al,
                       bf16* __restrict__ bh, bf16* __restrict__ bl,
                       int r, int w)
{
    const int P2 = ZP * ZP;
    int total = P2 + r * ZP + ZP * w;
    int i = blockIdx.x * blockDim.x + threadIdx.x;
    if (i >= total) return;
    if (i < P2) {
        int row = i / ZP, col = i - row * ZP;
        size_t s = (size_t)row * CW + col;
        bf16 h = crh[s], lo = crl[s];
        size_t da = (size_t)row * AK + col;
        ah[da] = h; al[da] = lo;
        bh[s] = h; bl[s] = lo;          // B pitch == CW
    } else if (i < P2 + r * ZP) {
        int j = i - P2;
        int row = j / ZP, col = j - row * ZP;
        size_t s = (size_t)(ZP + row) * CW + col;
        size_t d = (size_t)(ZP + r + row) * AK + col;
        ah[d] = crh[s]; al[d] = crl[s];
    } else {
        int j = i - P2 - r * ZP;
        int row = j / w, col = j - row * w;
        size_t s = (size_t)row * CW + ZP + col;
        size_t d = (size_t)row * CW + ZP + w + col;
        bh[d] = crh[s]; bl[d] = crl[s];
    }
}
// chain B = [Ystack | M32] planes
__global__ void kwcat(bf16* __restrict__ wh, bf16* __restrict__ wl,
                      const bf16* __restrict__ bh, const bf16* __restrict__ bl,
                      const bf16* __restrict__ crh, const bf16* __restrict__ crl)
{
    int i = blockIdx.x * blockDim.x + threadIdx.x;
    if (i >= ZP * CW) return;
    int row = i / CW, col = i - row * CW;
    bf16 h, lo;
    if (col < YW) { size_t s = (size_t)row * CW + ZP + col; h = bh[s]; lo = bl[s]; }
    else          { size_t s = (size_t)row * CW + (col - YW); h = crh[s]; lo = crl[s]; }
    wh[i] = h; wl[i] = lo;
}
__global__ void khbuild_bf(bf16* hh, bf16* hl, const float* NY, const float* Nm) {
    int idx = blockIdx.x * blockDim.x + threadIdx.x;
    if (idx >= XCW * YW) return;
    int row = idx >> 10, col = idx & 1023;
    int i = row >> 6, f = row & 63;
    int j = col >> 5, p = col & 31;
    float v = 0.f;
    if (j == i)      v = Nm[(size_t)f * ZP + 1536 + p];
    else if (j > i)  v = NY[(size_t)f * YW + (j - i - 1) * PP + p];
    bf16 h = __float2bfloat16(v);
    hh[(size_t)row * CW + col] = h;
    hl[(size_t)row * CW + col] = __float2bfloat16(v - __bfloat162float(h));
}
// Q plane region from V planes (A buffer rows 1600.., pitch AK)
__global__ void kqrev_bf(bf16* hh, bf16* hl, const bf16* vh, const bf16* vl) {
    int idx = blockIdx.x * blockDim.x + threadIdx.x;
    if (idx >= XCW * ZP) return;
    int row = idx / ZP, col = idx - row * ZP;
    int i = row >> 6, f = row & 63;
    size_t src = (size_t)((31 - i) * 64 + f) * AK + col;
    hh[(size_t)row * CW + YW + col] = vh[src];
    hl[(size_t)row * CW + YW + col] = vl[src];
}
__global__ void kout(float* out, const float* XC) {
    int i = blockIdx.x * blockDim.x + threadIdx.x;
    if (i >= BB * TT * PP) return;
    int b = i / (TT * PP), r = i - b * (TT * PP);
    int t = r >> 5, p = r & 31;
    int c = t >> 5, j = t & 31;
    out[i] = XC[((size_t)b * NCH + c) * CW + j * PP + p];
}
__global__ void ksplitP(const float* __restrict__ src, int lds,
                        bf16* __restrict__ hi, bf16* __restrict__ lo, int ldd,
                        int rows, int cols) {
    int i = blockIdx.x * blockDim.x + threadIdx.x;
    if (i >= rows * cols) return;
    int r = i / cols, c = i - r * cols;
    float v = src[(size_t)r * lds + c];
    bf16 h = __float2bfloat16(v);
    hi[(size_t)r * ldd + c] = h;
    lo[(size_t)r * ldd + c] = __float2bfloat16(v - __bfloat162float(h));
}
__global__ void kzplanes(bf16* h, bf16* l) {
    int i = blockIdx.x * blockDim.x + threadIdx.x;
    if (i >= BB * ZP) return;
    int c = i % ZP;
    h[i] = __float2bfloat16((c == HOM) ? 1.f : 0.f);
    l[i] = __float2bfloat16(0.f);
}

// ---------------- host ----------------
static void gemm(const float* A, int lda, const float* B, int ldb,
                 float* C, int ldc, int M, int N, int K, int acc)
{
    dim3 g((unsigned)((N + TBN - 1) / TBN), (unsigned)((M + TBM - 1) / TBM));
    tcgemm_k<<<g, 256, GSMEM>>>(A, lda, B, ldb, C, ldc, M, N, K, acc);
}
static void gemmF(const bf16* Ah, const bf16* Al, int lda,
                  const bf16* Bh, const bf16* Bl, int ldb,
                  float* C, int ldc, int M, int N, int K, int acc,
                  bf16* oh = nullptr, bf16* ol = nullptr, int opitch = 0, int ocol0 = 0)
{
    dim3 g((unsigned)((N + 127) / 128), (unsigned)((M + 127) / 128));
    gemm_bf<<<g, 256, GS2>>>(Ah, Al, lda, Bh, Bl, ldb, C, ldc, M, N, K, acc,
                             oh, ol, opitch, ocol0);
}
#define L1D(n) (((n) + 255) / 256), 256
static void splitP(const float* src, int lds, bf16* hi, bf16* lo, int ldd,
                   int rows, int cols) {
    ksplitP<<<L1D(rows * cols)>>>(src, lds, hi, lo, ldd, rows, cols);
}

extern "C" void kernel_launch(void* const* d_in, const int* in_sizes, int n_in,
                              void* d_out, int out_size)
{
    const float* x    = (const float*)d_in[0];
    const float* WA   = (const float*)d_in[1];
    const float* bA   = (const float*)d_in[2];
    const float* WB0  = (const float*)d_in[3];
    const float* bB0  = (const float*)d_in[4];
    const float* WBr  = (const float*)d_in[5];
    const float* bBr  = (const float*)d_in[6];
    const float* WC   = (const float*)d_in[7];
    const float* bC   = (const float*)d_in[8];
    const float* Wout = (const float*)d_in[9];
    const float* bout = (const float*)d_in[10];
    float* out = (float*)d_out;

    static int attr_done = 0;
    if (!attr_done) {
        cudaFuncSetAttribute(tcgemm_k, cudaFuncAttributeMaxDynamicSharedMemorySize, GSMEM);
        cudaFuncSetAttribute(gemm_bf,  cudaFuncAttributeMaxDynamicSharedMemorySize, GS2);
        attr_done = 1;
    }

    float *M_, *N_, *T1_, *T2_, *Y_, *NY_, *XC_;
    cudaGetSymbolAddress((void**)&M_,  gM);   cudaGetSymbolAddress((void**)&N_,  gN);
    cudaGetSymbolAddress((void**)&T1_, gT1);  cudaGetSymbolAddress((void**)&T2_, gT2);
    cudaGetSymbolAddress((void**)&Y_,  gY);   cudaGetSymbolAddress((void**)&NY_, gNY);
    cudaGetSymbolAddress((void**)&XC_, gXC);

    bf16 *Ah_, *Al_, *Bh_, *Bl_, *CRh_, *CRl_, *Wh_, *Wl_, *hh, *hl, *xh, *xl;
    bf16 *z0h, *z0l, *z1h, *z1l;
    cudaGetSymbolAddress((void**)&Ah_,  gAh);  cudaGetSymbolAddress((void**)&Al_,  gAl);
    cudaGetSymbolAddress((void**)&Bh_,  gBh);  cudaGetSymbolAddress((void**)&Bl_,  gBl);
    cudaGetSymbolAddress((void**)&CRh_, gCRh); cudaGetSymbolAddress((void**)&CRl_, gCRl);
    cudaGetSymbolAddress((void**)&Wh_,  gWh);  cudaGetSymbolAddress((void**)&Wl_,  gWl);
    cudaGetSymbolAddress((void**)&hh,   ghh);  cudaGetSymbolAddress((void**)&hl,   ghl);
    cudaGetSymbolAddress((void**)&xh,   gxh);  cudaGetSymbolAddress((void**)&xl,   gxl);
    cudaGetSymbolAddress((void**)&z0h,  gz0h); cudaGetSymbolAddress((void**)&z0l,  gz0l);
    cudaGetSymbolAddress((void**)&z1h,  gz1h); cudaGetSymbolAddress((void**)&z1l,  gz1l);

    const int W2 = UU * UU;

    // ---- build M and N (fp32 path) ----
    kzero<<<L1D(ZP*ZP)>>>(M_, ZP*ZP);
    kzero<<<L1D(64*ZP)>>>(N_, 64*ZP);

    kcopy<<<L1D(UU*UU)>>>(M_,                   ZP, WA,          UU, UU, UU);
    kcopy<<<L1D(PP*UU)>>>(M_ + (size_t)1536*ZP, ZP, WB0 + 64*UU, UU, PP, UU);
    kvadd2<<<L1D(UU)>>>(M_ + (size_t)HOM*ZP, bA, bB0, UU);
    kcopy<<<L1D(64*UU)>>>(N_,                   ZP, WB0,         UU, 64, UU);

    gemm(M_, ZP, WC, UU, T1_, UU, ZP, UU, UU, 0);
    kvaddrow<<<L1D(UU)>>>(T1_ + (size_t)HOM*UU, bC, UU);
    gemm(T1_, UU, WBr, UU, M_ + 512, ZP, ZP, UU, UU, 0);
    kaddb<<<L1D(UU*UU)>>>(M_ + (size_t)512*ZP + 512, ZP, WA + W2, UU, UU, UU);
    kvaddrow<<<L1D(UU)>>>(M_ + (size_t)HOM*ZP + 512, bA + UU, UU);
    kvaddrow<<<L1D(UU)>>>(M_ + (size_t)HOM*ZP + 512, bBr, UU);
    gemm(N_, ZP, WC, UU, T2_, UU, 64, UU, UU, 0);
    gemm(T2_, UU, WBr, UU, N_ + 512, ZP, 64, UU, UU, 0);

    gemm(M_ + 512, ZP, WC + W2, UU, T1_, UU, ZP, UU, UU, 0);
    kvaddrow<<<L1D(UU)>>>(T1_ + (size_t)HOM*UU, bC + UU, UU);
    gemm(T1_, UU, WBr + W2, UU, M_ + 1024, ZP, ZP, UU, UU, 0);
    kaddb<<<L1D(UU*UU)>>>(M_ + (size_t)1024*ZP + 1024, ZP, WA + 2*W2, UU, UU, UU);
    kvaddrow<<<L1D(UU)>>>(M_ + (size_t)HOM*ZP + 1024, bA + 2*UU, UU);
    kvaddrow<<<L1D(UU)>>>(M_ + (size_t)HOM*ZP + 1024, bBr + UU, UU);
    gemm(N_ + 512, ZP, WC + W2, UU, T2_, UU, 64, UU, UU, 0);
    gemm(T2_, UU, WBr + W2, UU, N_ + 1024, ZP, 64, UU, UU, 0);

    gemm(M_ + 1024, ZP, WC + 2*W2, UU, T1_, UU, ZP, UU, UU, 0);
    kvaddrow<<<L1D(UU)>>>(T1_ + (size_t)HOM*UU, bC + 2*UU, UU);
    gemm(T1_, UU, Wout, PP, M_ + 1536, ZP, ZP, PP, UU, 0);
    kvaddrow<<<L1D(PP)>>>(M_ + (size_t)HOM*ZP + 1536, bout, PP);
    kcopy<<<L1D(ZP*PP)>>>(Y_, PP, M_ + 1536, ZP, ZP, PP);   // D seed
    kdiag<<<1, 64>>>(M_);
    gemm(N_ + 1024, ZP, WC + 2*W2, UU, T2_, UU, 64, UU, UU, 0);
    gemm(T2_, UU, Wout, PP, N_ + 1536, ZP, 64, PP, UU, 0);

    // x split early (independent)
    splitP(x, XCW, xh, xl, XCW, MROW, XCW);

    // ---- seed planes: A = [M; V_0=N], B = [M | Y_0=D] ----
    splitP(M_, ZP, Ah_, Al_, AK, ZP, ZP);
    splitP(N_, ZP, Ah_ + (size_t)ZP*AK, Al_ + (size_t)ZP*AK, AK, 64, ZP);
    splitP(M_, ZP, Bh_, Bl_, CW, ZP, ZP);
    splitP(Y_, PP, Bh_ + ZP, Bl_ + ZP, CW, ZP, PP);

    // ---- merged doubling rounds: 1 plane-GEMM + 1 redistribute per round ----
    for (int d = 0; d < 5; ++d) {
        const int w = 32 << d, r = 64 << d;
        gemmF(Ah_, Al_, AK, Bh_, Bl_, CW, nullptr, 0,
              ZP + r, ZP + w, ZP, 0, CRh_, CRl_, CW, 0);
        int total = ZP*ZP + r*ZP + ZP*w;
        kround<<<L1D(total)>>>(CRh_, CRl_, Ah_, Al_, Bh_, Bl_, r, w);
    }
    // CR now holds M^32 (power region); A rows 1600.. = V stack; B cols 1600.. = Y stack

    // ---- chain B = [Ystack | M32] ----
    kwcat<<<L1D(ZP*CW)>>>(Wh_, Wl_, Bh_, Bl_, CRh_, CRl_);

    // ---- NY = N @ Ystack (plane GEMM); Hcat planes ----
    gemmF(Ah_ + (size_t)ZP*AK, Al_ + (size_t)ZP*AK, AK,
          Bh_ + ZP, Bl_ + ZP, CW, NY_, YW, 64, YW, ZP, 0);
    khbuild_bf<<<L1D(XCW*YW)>>>(hh, hl, NY_, N_);
    kqrev_bf<<<L1D(XCW*ZP)>>>(hh, hl, Ah_ + (size_t)ZP*AK, Al_ + (size_t)ZP*AK);

    // ---- giant x-driven GEMM: XC = X * Hcat (8192 x 2624 x 2048) ----
    gemmF(xh, xl, XCW, hh, hl, CW, XC_, CW, MROW, CW, XCW, 0);

    // ---- serial z-chain (wide N=CW, fused z-plane epilogue) ----
    kzplanes<<<L1D(BB*ZP)>>>(z0h, z0l);
    for (int c = 0; c < NCH; ++c) {
        const bf16* ah = (c & 1) ? z1h : z0h;
        const bf16* al = (c & 1) ? z1l : z0l;
        bf16* oh = (c & 1) ? z0h : z1h;
        bf16* ol = (c & 1) ? z0l : z1l;
        gemmF(ah, al, ZP, Wh_, Wl_, CW, XC_ + (size_t)c * CW, NCH * CW,
              BB, CW, ZP, 1, oh, ol, ZP, YW);
    }

    // ---- scatter y-part to output ----
    kout<<<L1D(BB*TT*PP)>>>(out, XC_);
}

// round 16
// speedup vs baseline: 1.3900x; 1.1028x over previous
#include <cuda_runtime.h>
#include <cuda_bf16.h>
#include <cstdint>
#include <cstddef>

// Problem constants
#define BB 512
#define TT 512
#define FF 64
#define PP 32
#define UU 512

// Affine-state formulation
#define ZP   1600
#define HOM  1568
#define CH   32
#define NCH  (TT/CH)
#define XCW  (CH*FF)       // 2048
#define YW   (CH*PP)       // 1024
#define MROW (BB*NCH)      // 8192
#define CW   (YW+ZP)       // 2624
#define AK   1600          // A-plane pitch
#define ARR  3648          // A-plane rows (1600 power + 2048 V stack)
#define MNR  1664          // merged [M; N] rows

typedef unsigned long long u64;
typedef __nv_bfloat16 bf16;

// ---------------- fp32 scratch ----------------
__device__ __align__(256) float gMN[(size_t)MNR*ZP];   // rows 0-1599: M, 1600-1663: N
__device__ __align__(256) float gT1[(size_t)MNR*UU];
__device__ __align__(256) float gY[ZP*PP];
__device__ __align__(256) float gNY[64*YW];
__device__ __align__(256) float gXC[(size_t)MROW*CW];

// ---------------- bf16 planes ----------------
__device__ __align__(256) bf16 gAh[(size_t)ARR*AK], gAl[(size_t)ARR*AK];   // [power; V stack]
__device__ __align__(256) bf16 gBh[(size_t)ZP*CW],  gBl[(size_t)ZP*CW];    // [power | Y stack]
__device__ __align__(256) bf16 gCRh[(size_t)2624*CW], gCRl[(size_t)2624*CW]; // round output
__device__ __align__(256) bf16 gWh[(size_t)ZP*CW],  gWl[(size_t)ZP*CW];    // chain B = [Y | M32]
__device__ __align__(256) bf16 ghh[(size_t)XCW*CW], ghl[(size_t)XCW*CW];   // Hcat planes
__device__ __align__(256) bf16 gxh[(size_t)MROW*XCW], gxl[(size_t)MROW*XCW];
__device__ __align__(256) bf16 gz0h[BB*ZP], gz0l[BB*ZP], gz1h[BB*ZP], gz1l[BB*ZP];

// ================= PTX helpers =================
__device__ __forceinline__ uint32_t bfpack(float x, float y) {  // lo=x, hi=y
    uint32_t r;
    asm("cvt.rn.bf16x2.f32 %0, %1, %2;" : "=r"(r) : "f"(y), "f"(x));
    return r;
}
__device__ __forceinline__ void ldsm4(uint32_t& r0, uint32_t& r1,
                                      uint32_t& r2, uint32_t& r3, uint32_t a) {
    asm volatile("ldmatrix.sync.aligned.m8n8.x4.shared.b16 {%0,%1,%2,%3}, [%4];"
                 : "=r"(r0), "=r"(r1), "=r"(r2), "=r"(r3) : "r"(a));
}
__device__ __forceinline__ void ldsm4t(uint32_t& r0, uint32_t& r1,
                                       uint32_t& r2, uint32_t& r3, uint32_t a) {
    asm volatile("ldmatrix.sync.aligned.m8n8.x4.trans.shared.b16 {%0,%1,%2,%3}, [%4];"
                 : "=r"(r0), "=r"(r1), "=r"(r2), "=r"(r3) : "r"(a));
}
__device__ __forceinline__ void mma16816(float* c, const uint32_t* a, const uint32_t* b) {
    asm volatile("mma.sync.aligned.m16n8k16.row.col.f32.bf16.bf16.f32 "
                 "{%0,%1,%2,%3}, {%4,%5,%6,%7}, {%8,%9}, {%0,%1,%2,%3};"
                 : "+f"(c[0]), "+f"(c[1]), "+f"(c[2]), "+f"(c[3])
                 : "r"(a[0]), "r"(a[1]), "r"(a[2]), "r"(a[3]),
                   "r"(b[0]), "r"(b[1]));
}
__device__ __forceinline__ void cpa16(uint32_t d, const void* g, int bytes) {
    asm volatile("cp.async.cg.shared.global [%0], [%1], 16, %2;"
                 :: "r"(d), "l"(g), "r"(bytes));
}
__device__ __forceinline__ void cpcommit() { asm volatile("cp.async.commit_group;"); }
template<int n> __device__ __forceinline__ void cpwait() {
    asm volatile("cp.async.wait_group %0;" :: "n"(n));
}

// ================= pre-split bf16 GEMM (2 CTAs/SM) =================
#define S2   2
#define AROW 80
#define BROW 272
#define A_T  (128*AROW)
#define B_T  (32*BROW)
#define SLOT (2*A_T + 2*B_T)
#define GS2  (S2*SLOT)              // 75776 B -> 2 CTAs/SM

__device__ __forceinline__ void issue_stage(
    uint32_t sb, int s, int m0, int n0, int M, int N, int lda, int ldb,
    const bf16* __restrict__ Ah, const bf16* __restrict__ Al,
    const bf16* __restrict__ Bh, const bf16* __restrict__ Bl, int tid)
{
    const int k0 = s * 32;
    const uint32_t sl = sb + (uint32_t)((s % S2) * SLOT);
#pragma unroll
    for (int q = 0; q < 2; ++q) {
        int c = tid + q * 256;
        int m = c >> 2, kc = c & 3;
        int row = m0 + m;
        int bytes = (row < M) ? 16 : 0;
        int rs = bytes ? row : 0;
        const bf16* s1 = Ah + (size_t)rs * lda + k0 + kc * 8;
        const bf16* s2 = Al + (size_t)rs * lda + k0 + kc * 8;
        cpa16(sl + m * AROW + kc * 16, s1, bytes);
        cpa16(sl + A_T + m * AROW + kc * 16, s2, bytes);
    }
#pragma unroll
    for (int q = 0; q < 2; ++q) {
        int c = tid + q * 256;
        int k = c >> 4, nc = c & 15;
        int col = n0 + nc * 8;
        int bytes = (col < N) ? 16 : 0;
        int cs = bytes ? col : 0;
        const bf16* s1 = Bh + (size_t)(k0 + k) * ldb + cs;
        const bf16* s2 = Bl + (size_t)(k0 + k) * ldb + cs;
        cpa16(sl + 2 * A_T + k * BROW + nc * 16, s1, bytes);
        cpa16(sl + 2 * A_T + B_T + k * BROW + nc * 16, s2, bytes);
    }
    cpcommit();
}

// C (fp32, optional) and/or bf16 hi/lo plane output (cols >= ocol0, shifted).
__global__ void __launch_bounds__(256, 2) gemm_bf(
    const bf16* __restrict__ Ah, const bf16* __restrict__ Al, int lda,
    const bf16* __restrict__ Bh, const bf16* __restrict__ Bl, int ldb,
    float* __restrict__ C, int ldc, int M, int N, int K, int accum,
    bf16* __restrict__ oh, bf16* __restrict__ ol, int opitch, int ocol0)
{
    extern __shared__ __align__(16) char smem[];
    const uint32_t sb = (uint32_t)__cvta_generic_to_shared(smem);
    const int tid  = threadIdx.x;
    const int wid  = tid >> 5;
    const int lane = tid & 31;
    const int m0 = blockIdx.y * 128;
    const int n0 = blockIdx.x * 128;
    const int wm = (wid >> 2) * 64;
    const int wn = (wid & 3) * 32;

    float acc[4][4][4];
#pragma unroll
    for (int mi = 0; mi < 4; ++mi)
#pragma unroll
        for (int ni = 0; ni < 4; ++ni)
#pragma unroll
            for (int r = 0; r < 4; ++r) acc[mi][ni][r] = 0.f;

    const int nk = K / 32;
    const int pro = (S2 - 1 < nk) ? S2 - 1 : nk;
    for (int s = 0; s < pro; ++s)
        issue_stage(sb, s, m0, n0, M, N, lda, ldb, Ah, Al, Bh, Bl, tid);

    const uint32_t a_lrow = (uint32_t)(lane & 15);
    const uint32_t a_lchk = (uint32_t)(lane >> 4);
    const uint32_t b_krow = (uint32_t)(lane & 15);
    const uint32_t b_ncol = (uint32_t)((lane >> 4) * 8);

    for (int s = 0; s < nk; ++s) {
        cpwait<S2 - 2>();
        __syncthreads();
        if (s + S2 - 1 < nk)
            issue_stage(sb, s + S2 - 1, m0, n0, M, N, lda, ldb, Ah, Al, Bh, Bl, tid);

        const uint32_t base = sb + (uint32_t)((s % S2) * SLOT);
#pragma unroll
        for (int kk = 0; kk < 2; ++kk) {
            uint32_t ah[4][4], al[4][4], bh[4][2], bl[4][2];
#pragma unroll
            for (int mi = 0; mi < 4; ++mi) {
                uint32_t off = (uint32_t)(wm + mi * 16 + a_lrow) * AROW
                             + (uint32_t)(kk * 2 + a_lchk) * 16;
                ldsm4(ah[mi][0], ah[mi][1], ah[mi][2], ah[mi][3], base + off);
                ldsm4(al[mi][0], al[mi][1], al[mi][2], al[mi][3], base + A_T + off);
            }
#pragma unroll
            for (int h = 0; h < 2; ++h) {
                uint32_t off = (uint32_t)(kk * 16 + b_krow) * BROW
                             + (uint32_t)(wn + h * 16 + b_ncol) * 2;
                uint32_t t0, t1, t2, t3;
                ldsm4t(t0, t1, t2, t3, base + 2 * A_T + off);
                bh[2*h][0] = t0; bh[2*h][1] = t1; bh[2*h+1][0] = t2; bh[2*h+1][1] = t3;
                ldsm4t(t0, t1, t2, t3, base + 2 * A_T + B_T + off);
                bl[2*h][0] = t0; bl[2*h][1] = t1; bl[2*h+1][0] = t2; bl[2*h+1][1] = t3;
            }
#pragma unroll
            for (int mi = 0; mi < 4; ++mi)
#pragma unroll
                for (int ni = 0; ni < 4; ++ni) {
                    mma16816(acc[mi][ni], ah[mi], bh[ni]);
                    mma16816(acc[mi][ni], ah[mi], bl[ni]);
                    mma16816(acc[mi][ni], al[mi], bh[ni]);
                }
        }
    }

#pragma unroll
    for (int mi = 0; mi < 4; ++mi) {
        int r0 = m0 + wm + mi * 16 + (lane >> 2);
        int r1 = r0 + 8;
#pragma unroll
        for (int ni = 0; ni < 4; ++ni) {
            int cc = n0 + wn + ni * 8 + (lane & 3) * 2;
            if (cc < N) {
#pragma unroll
                for (int hh2 = 0; hh2 < 2; ++hh2) {
                    int row = hh2 ? r1 : r0;
                    if (row < M) {
                        float vx = acc[mi][ni][hh2 * 2];
                        float vy = acc[mi][ni][hh2 * 2 + 1];
                        if (C) {
                            float2* p = reinterpret_cast<float2*>(&C[(size_t)row * ldc + cc]);
                            if (accum) { float2 v = *p; vx += v.x; vy += v.y; }
                            *p = make_float2(vx, vy);
                        }
                        if (oh && cc >= ocol0) {
                            float hx = __bfloat162float(__float2bfloat16(vx));
                            float hy = __bfloat162float(__float2bfloat16(vy));
                            size_t oidx = (size_t)row * opitch + (cc - ocol0);
                            *reinterpret_cast<uint32_t*>(oh + oidx) = bfpack(vx, vy);
                            *reinterpret_cast<uint32_t*>(ol + oidx) = bfpack(vx - hx, vy - hy);
                        }
                    }
                }
            }
        }
    }
}

// ================= slow path: fp32-input GEMM (small builds) ==
#define TBM 128
#define TBN 128
#define TBK 32
#define ROWB 80
#define TILEB (128*ROWB)
#define BUFB (4*TILEB)
#define GSMEM (2*BUFB)

__device__ __forceinline__ void ldg_tiles(
    const float* __restrict__ A, int lda, int M, int m0,
    const float* __restrict__ B, int ldb, int N, int n0,
    int k0, int smr, int kh, float4 ra[4], float rb[16])
{
    const float4 z4 = make_float4(0.f, 0.f, 0.f, 0.f);
    if (m0 + smr < M) {
        const float* ap = A + (size_t)(m0 + smr) * lda + k0 + kh;
#pragma unroll
        for (int j = 0; j < 4; ++j)
            ra[j] = *reinterpret_cast<const float4*>(ap + 4 * j);
    } else {
#pragma unroll
        for (int j = 0; j < 4; ++j) ra[j] = z4;
    }
    if (n0 + smr < N) {
        const float* bp = B + (size_t)(k0 + kh) * ldb + (n0 + smr);
#pragma unroll
        for (int j = 0; j < 16; ++j) rb[j] = bp[(size_t)j * ldb];
    } else {
#pragma unroll
        for (int j = 0; j < 16; ++j) rb[j] = 0.f;
    }
}
__device__ __forceinline__ void split8(const float* v, uint32_t* hw, uint32_t* lw) {
#pragma unroll
    for (int j = 0; j < 8; ++j) {
        float x = v[2 * j], y = v[2 * j + 1];
        float hx = __bfloat162float(__float2bfloat16(x));
        float hy = __bfloat162float(__float2bfloat16(y));
        hw[j] = bfpack(x, y);
        lw[j] = bfpack(x - hx, y - hy);
    }
}
__device__ __forceinline__ void sts_tiles(char* smem, int buf, int smr, int kh,
                                          const float4 ra[4], const float rb[16])
{
    char* base = smem + buf * BUFB;
    uint32_t hw[8], lw[8];
    float av[16];
#pragma unroll
    for (int j = 0; j < 4; ++j) {
        av[4*j] = ra[j].x; av[4*j+1] = ra[j].y; av[4*j+2] = ra[j].z; av[4*j+3] = ra[j].w;
    }
    split8(av, hw, lw);
    {
        char* d = base + smr * ROWB + kh * 2;
        *reinterpret_cast<uint4*>(d)      = make_uint4(hw[0], hw[1], hw[2], hw[3]);
        *reinterpret_cast<uint4*>(d + 16) = make_uint4(hw[4], hw[5], hw[6], hw[7]);
        char* d2 = d + TILEB;
        *reinterpret_cast<uint4*>(d2)      = make_uint4(lw[0], lw[1], lw[2], lw[3]);
        *reinterpret_cast<uint4*>(d2 + 16) = make_uint4(lw[4], lw[5], lw[6], lw[7]);
    }
    split8(rb, hw, lw);
    {
        char* d = base + 2 * TILEB + smr * ROWB + kh * 2;
        *reinterpret_cast<uint4*>(d)      = make_uint4(hw[0], hw[1], hw[2], hw[3]);
        *reinterpret_cast<uint4*>(d + 16) = make_uint4(hw[4], hw[5], hw[6], hw[7]);
        char* d2 = d + TILEB;
        *reinterpret_cast<uint4*>(d2)      = make_uint4(lw[0], lw[1], lw[2], lw[3]);
        *reinterpret_cast<uint4*>(d2 + 16) = make_uint4(lw[4], lw[5], lw[6], lw[7]);
    }
}

__global__ void __launch_bounds__(256, 1) tcgemm_k(
    const float* __restrict__ A, int lda,
    const float* __restrict__ B, int ldb,
    float* __restrict__ C, int ldc,
    int M, int N, int K, int accum)
{
    extern __shared__ __align__(16) char smem[];
    const uint32_t sb = (uint32_t)__cvta_generic_to_shared(smem);
    const int tid  = threadIdx.x;
    const int wid  = tid >> 5;
    const int lane = tid & 31;
    const int m0 = blockIdx.y * TBM;
    const int n0 = blockIdx.x * TBN;
    const int wm = (wid >> 2) * 64;
    const int wn = (wid & 3) * 32;
    const int smr = tid >> 1;
    const int kh  = (tid & 1) * 16;

    float acc[4][4][4];
#pragma unroll
    for (int mi = 0; mi < 4; ++mi)
#pragma unroll
        for (int ni = 0; ni < 4; ++ni)
#pragma unroll
            for (int r = 0; r < 4; ++r) acc[mi][ni][r] = 0.f;

    const uint32_t a_lrow = (uint32_t)(lane & 15);
    const uint32_t a_lchk = (uint32_t)(lane >> 4);
    const uint32_t b_lrow = (uint32_t)(((lane >> 4) << 3) + (lane & 7));
    const uint32_t b_lchk = (uint32_t)((lane >> 3) & 1);

    const int nk = K / TBK;
    float4 ra[4]; float rb[16];
    ldg_tiles(A, lda, M, m0, B, ldb, N, n0, 0, smr, kh, ra, rb);
    sts_tiles(smem, 0, smr, kh, ra, rb);
    __syncthreads();

    for (int s = 0; s < nk; ++s) {
        if (s + 1 < nk)
            ldg_tiles(A, lda, M, m0, B, ldb, N, n0, (s + 1) * TBK, smr, kh, ra, rb);
        const uint32_t base = sb + (uint32_t)((s & 1) * BUFB);
#pragma unroll
        for (int kk = 0; kk < 2; ++kk) {
            uint32_t ah[4][4], al[4][4], bh[4][2], bl[4][2];
#pragma unroll
            for (int mi = 0; mi < 4; ++mi) {
                uint32_t off = (uint32_t)(wm + mi * 16 + a_lrow) * ROWB
                             + (uint32_t)(kk * 2 + a_lchk) * 16;
                ldsm4(ah[mi][0], ah[mi][1], ah[mi][2], ah[mi][3], base + off);
                ldsm4(al[mi][0], al[mi][1], al[mi][2], al[mi][3], base + TILEB + off);
            }
#pragma unroll
            for (int h = 0; h < 2; ++h) {
                uint32_t off = (uint32_t)(wn + h * 16 + b_lrow) * ROWB
                             + (uint32_t)(kk * 2 + b_lchk) * 16;
                uint32_t t0, t1, t2, t3;
                ldsm4(t0, t1, t2, t3, base + 2 * TILEB + off);
                bh[2*h][0] = t0; bh[2*h][1] = t1; bh[2*h+1][0] = t2; bh[2*h+1][1] = t3;
                ldsm4(t0, t1, t2, t3, base + 3 * TILEB + off);
                bl[2*h][0] = t0; bl[2*h][1] = t1; bl[2*h+1][0] = t2; bl[2*h+1][1] = t3;
            }
#pragma unroll
            for (int mi = 0; mi < 4; ++mi)
#pragma unroll
                for (int ni = 0; ni < 4; ++ni) {
                    mma16816(acc[mi][ni], ah[mi], bh[ni]);
                    mma16816(acc[mi][ni], ah[mi], bl[ni]);
                    mma16816(acc[mi][ni], al[mi], bh[ni]);
                }
        }
        __syncthreads();
        if (s + 1 < nk) {
            sts_tiles(smem, (s + 1) & 1, smr, kh, ra, rb);
            __syncthreads();
        }
    }
#pragma unroll
    for (int mi = 0; mi < 4; ++mi) {
        int r0 = m0 + wm + mi * 16 + (lane >> 2);
        int r1 = r0 + 8;
#pragma unroll
        for (int ni = 0; ni < 4; ++ni) {
            int cc = n0 + wn + ni * 8 + (lane & 3) * 2;
            if (cc < N) {
                if (r0 < M) {
                    float2* p = reinterpret_cast<float2*>(&C[(size_t)r0 * ldc + cc]);
                    float2 v = accum ? *p : make_float2(0.f, 0.f);
                    v.x += acc[mi][ni][0]; v.y += acc[mi][ni][1];
                    *p = v;
                }
                if (r1 < M) {
                    float2* p = reinterpret_cast<float2*>(&C[(size_t)r1 * ldc + cc]);
                    float2 v = accum ? *p : make_float2(0.f, 0.f);
                    v.x += acc[mi][ni][2]; v.y += acc[mi][ni][3];
                    *p = v;
                }
            }
        }
    }
}

// ---------------- small helper kernels ----------------
__global__ void kzero(float* p, int n) {
    int i = blockIdx.x * blockDim.x + threadIdx.x;
    if (i < n) p[i] = 0.f;
}
__global__ void kcopy(float* dst, int ldd, const float* src, int lds, int rows, int cols) {
    int i = blockIdx.x * blockDim.x + threadIdx.x;
    if (i >= rows * cols) return;
    int r = i / cols, c = i - r * cols;
    dst[(size_t)r * ldd + c] = src[(size_t)r * lds + c];
}
__global__ void kaddb(float* dst, int ldd, const float* src, int lds, int rows, int cols) {
    int i = blockIdx.x * blockDim.x + threadIdx.x;
    if (i >= rows * cols) return;
    int r = i / cols, c = i - r * cols;
    dst[(size_t)r * ldd + c] += src[(size_t)r * lds + c];
}
__global__ void kvadd2(float* dst, const float* a, const float* b, int n) {
    int i = blockIdx.x * blockDim.x + threadIdx.x;
    if (i < n) dst[i] = a[i] + b[i];
}
__global__ void kvaddrow(float* dst, const float* src, int n) {
    int i = blockIdx.x * blockDim.x + threadIdx.x;
    if (i < n) dst[i] += src[i];
}
__global__ void kdiag(float* M) {
    int i = threadIdx.x;
    if (i < PP) M[(size_t)(1536 + i) * ZP + 1536 + i] += 1.f;
    if (i == PP) M[(size_t)HOM * ZP + HOM] += 1.f;
}
// Redistribute round output planes: power -> A & B, V append -> A, Y append -> B
__global__ void kround(const bf16* __restrict__ crh, const bf16* __restrict__ crl,
                       bf16* __restrict__ ah, bf16* __restrict__ al,
                       bf16* __restrict__ bh, bf16* __restrict__ bl,
                       int r, int w)
{
    const int P2 = ZP * ZP;
    int total = P2 + r * ZP + ZP * w;
    int i = blockIdx.x * blockDim.x + threadIdx.x;
    if (i >= total) return;
    if (i < P2) {
        int row = i / ZP, col = i - row * ZP;
        size_t s = (size_t)row * CW + col;
        bf16 h = crh[s], lo = crl[s];
        size_t da = (size_t)row * AK + col;
        ah[da] = h; al[da] = lo;
        bh[s] = h; bl[s] = lo;          // B pitch == CW
    } else if (i < P2 + r * ZP) {
        int j = i - P2;
        int row = j / ZP, col = j - row * ZP;
        size_t s = (size_t)(ZP + row) * CW + col;
        size_t d = (size_t)(ZP + r + row) * AK + col;
        ah[d] = crh[s]; al[d] = crl[s];
    } else {
        int j = i - P2 - r * ZP;
        int row = j / w, col = j - row * w;
        size_t s = (size_t)row * CW + ZP + col;
        size_t d = (size_t)row * CW + ZP + w + col;
        bh[d] = crh[s]; bl[d] = crl[s];
    }
}
// chain B = [Ystack | M32] planes
__global__ void kwcat(bf16* __restrict__ wh, bf16* __restrict__ wl,
                      const bf16* __restrict__ bh, const bf16* __restrict__ bl,
                      const bf16* __restrict__ crh, const bf16* __restrict__ crl)
{
    int i = blockIdx.x * blockDim.x + threadIdx.x;
    if (i >= ZP * CW) return;
    int row = i / CW, col = i - row * CW;
    bf16 h, lo;
    if (col < YW) { size_t s = (size_t)row * CW + ZP + col; h = bh[s]; lo = bl[s]; }
    else          { size_t s = (size_t)row * CW + (col - YW); h = crh[s]; lo = crl[s]; }
    wh[i] = h; wl[i] = lo;
}
__global__ void khbuild_bf(bf16* hh, bf16* hl, const float* NY, const float* Nm) {
    int idx = blockIdx.x * blockDim.x + threadIdx.x;
    if (idx >= XCW * YW) return;
    int row = idx >> 10, col = idx & 1023;
    int i = row >> 6, f = row & 63;
    int j = col >> 5, p = col & 31;
    float v = 0.f;
    if (j == i)      v = Nm[(size_t)f * ZP + 1536 + p];
    else if (j > i)  v = NY[(size_t)f * YW + (j - i - 1) * PP + p];
    bf16 h = __float2bfloat16(v);
    hh[(size_t)row * CW + col] = h;
    hl[(size_t)row * CW + col] = __float2bfloat16(v - __bfloat162float(h));
}
// Q plane region from V planes (A buffer rows 1600.., pitch AK)
__global__ void kqrev_bf(bf16* hh, bf16* hl, const bf16* vh, const bf16* vl) {
    int idx = blockIdx.x * blockDim.x + threadIdx.x;
    if (idx >= XCW * ZP) return;
    int row = idx / ZP, col = idx - row * ZP;
    int i = row >> 6, f = row & 63;
    size_t src = (size_t)((31 - i) * 64 + f) * AK + col;
    hh[(size_t)row * CW + YW + col] = vh[src];
    hl[(size_t)row * CW + YW + col] = vl[src];
}
__global__ void kout(float* out, const float* XC) {
    int i = blockIdx.x * blockDim.x + threadIdx.x;
    if (i >= BB * TT * PP) return;
    int b = i / (TT * PP), r = i - b * (TT * PP);
    int t = r >> 5, p = r & 31;
    int c = t >> 5, j = t & 31;
    out[i] = XC[((size_t)b * NCH + c) * CW + j * PP + p];
}
__global__ void ksplitP(const float* __restrict__ src, int lds,
                        bf16* __restrict__ hi, bf16* __restrict__ lo, int ldd,
                        int rows, int cols) {
    int i = blockIdx.x * blockDim.x + threadIdx.x;
    if (i >= rows * cols) return;
    int r = i / cols, c = i - r * cols;
    float v = src[(size_t)r * lds + c];
    bf16 h = __float2bfloat16(v);
    hi[(size_t)r * ldd + c] = h;
    lo[(size_t)r * ldd + c] = __float2bfloat16(v - __bfloat162float(h));
}
__global__ void kzplanes(bf16* h, bf16* l) {
    int i = blockIdx.x * blockDim.x + threadIdx.x;
    if (i >= BB * ZP) return;
    int c = i % ZP;
    h[i] = __float2bfloat16((c == HOM) ? 1.f : 0.f);
    l[i] = __float2bfloat16(0.f);
}

// ---------------- host ----------------
static void gemm(const float* A, int lda, const float* B, int ldb,
                 float* C, int ldc, int M, int N, int K, int acc)
{
    dim3 g((unsigned)((N + TBN - 1) / TBN), (unsigned)((M + TBM - 1) / TBM));
    tcgemm_k<<<g, 256, GSMEM>>>(A, lda, B, ldb, C, ldc, M, N, K, acc);
}
static void gemmF(const bf16* Ah, const bf16* Al, int lda,
                  const bf16* Bh, const bf16* Bl, int ldb,
                  float* C, int ldc, int M, int N, int K, int acc,
                  bf16* oh = nullptr, bf16* ol = nullptr, int opitch = 0, int ocol0 = 0)
{
    dim3 g((unsigned)((N + 127) / 128), (unsigned)((M + 127) / 128));
    gemm_bf<<<g, 256, GS2>>>(Ah, Al, lda, Bh, Bl, ldb, C, ldc, M, N, K, acc,
                             oh, ol, opitch, ocol0);
}
#define L1D(n) (((n) + 255) / 256), 256
static void splitP(const float* src, int lds, bf16* hi, bf16* lo, int ldd,
                   int rows, int cols) {
    ksplitP<<<L1D(rows * cols)>>>(src, lds, hi, lo, ldd, rows, cols);
}

extern "C" void kernel_launch(void* const* d_in, const int* in_sizes, int n_in,
                              void* d_out, int out_size)
{
    const float* x    = (const float*)d_in[0];
    const float* WA   = (const float*)d_in[1];
    const float* bA   = (const float*)d_in[2];
    const float* WB0  = (const float*)d_in[3];
    const float* bB0  = (const float*)d_in[4];
    const float* WBr  = (const float*)d_in[5];
    const float* bBr  = (const float*)d_in[6];
    const float* WC   = (const float*)d_in[7];
    const float* bC   = (const float*)d_in[8];
    const float* Wout = (const float*)d_in[9];
    const float* bout = (const float*)d_in[10];
    float* out = (float*)d_out;

    static int attr_done = 0;
    if (!attr_done) {
        cudaFuncSetAttribute(tcgemm_k, cudaFuncAttributeMaxDynamicSharedMemorySize, GSMEM);
        cudaFuncSetAttribute(gemm_bf,  cudaFuncAttributeMaxDynamicSharedMemorySize, GS2);
        attr_done = 1;
    }

    float *MN_, *T1_, *Y_, *NY_, *XC_;
    cudaGetSymbolAddress((void**)&MN_, gMN);  cudaGetSymbolAddress((void**)&T1_, gT1);
    cudaGetSymbolAddress((void**)&Y_,  gY);   cudaGetSymbolAddress((void**)&NY_, gNY);
    cudaGetSymbolAddress((void**)&XC_, gXC);

    bf16 *Ah_, *Al_, *Bh_, *Bl_, *CRh_, *CRl_, *Wh_, *Wl_, *hh, *hl, *xh, *xl;
    bf16 *z0h, *z0l, *z1h, *z1l;
    cudaGetSymbolAddress((void**)&Ah_,  gAh);  cudaGetSymbolAddress((void**)&Al_,  gAl);
    cudaGetSymbolAddress((void**)&Bh_,  gBh);  cudaGetSymbolAddress((void**)&Bl_,  gBl);
    cudaGetSymbolAddress((void**)&CRh_, gCRh); cudaGetSymbolAddress((void**)&CRl_, gCRl);
    cudaGetSymbolAddress((void**)&Wh_,  gWh);  cudaGetSymbolAddress((void**)&Wl_,  gWl);
    cudaGetSymbolAddress((void**)&hh,   ghh);  cudaGetSymbolAddress((void**)&hl,   ghl);
    cudaGetSymbolAddress((void**)&xh,   gxh);  cudaGetSymbolAddress((void**)&xl,   gxl);
    cudaGetSymbolAddress((void**)&z0h,  gz0h); cudaGetSymbolAddress((void**)&z0l,  gz0l);
    cudaGetSymbolAddress((void**)&z1h,  gz1h); cudaGetSymbolAddress((void**)&z1l,  gz1l);

    const int W2 = UU * UU;
    float* Nrow = MN_ + (size_t)1600 * ZP;   // N block (rows 1600-1663)

    // ---- build merged MN = [M; N] (fp32 path, halved GEMM count) ----
    kzero<<<L1D(MNR*ZP)>>>(MN_, MNR*ZP);

    // column block h1'
    kcopy<<<L1D(UU*UU)>>>(MN_,                   ZP, WA,          UU, UU, UU);
    kcopy<<<L1D(PP*UU)>>>(MN_ + (size_t)1536*ZP, ZP, WB0 + 64*UU, UU, PP, UU);
    kvadd2<<<L1D(UU)>>>(MN_ + (size_t)HOM*ZP, bA, bB0, UU);
    kcopy<<<L1D(64*UU)>>>(Nrow,                  ZP, WB0,         UU, 64, UU);

    // layer transitions l=0,1: both M and N blocks in one GEMM pair
    for (int l = 0; l < 2; ++l) {
        gemm(MN_ + l * 512, ZP, WC + (size_t)l * W2, UU, T1_, UU, MNR, UU, UU, 0);
        kvaddrow<<<L1D(UU)>>>(T1_ + (size_t)HOM*UU, bC + l*UU, UU);
        gemm(T1_, UU, WBr + (size_t)l * W2, UU, MN_ + (l + 1) * 512, ZP, MNR, UU, UU, 0);
        kaddb<<<L1D(UU*UU)>>>(MN_ + (size_t)(l+1)*512*ZP + (l+1)*512, ZP,
                              WA + (size_t)(l+1)*W2, UU, UU, UU);
        kvaddrow<<<L1D(UU)>>>(MN_ + (size_t)HOM*ZP + (l+1)*512, bA + (l+1)*UU, UU);
        kvaddrow<<<L1D(UU)>>>(MN_ + (size_t)HOM*ZP + (l+1)*512, bBr + l*UU, UU);
    }

    // acc column block
    gemm(MN_ + 1024, ZP, WC + (size_t)2*W2, UU, T1_, UU, MNR, UU, UU, 0);
    kvaddrow<<<L1D(UU)>>>(T1_ + (size_t)HOM*UU, bC + 2*UU, UU);
    gemm(T1_, UU, Wout, PP, MN_ + 1536, ZP, MNR, PP, UU, 0);
    kvaddrow<<<L1D(PP)>>>(MN_ + (size_t)HOM*ZP + 1536, bout, PP);
    kcopy<<<L1D(ZP*PP)>>>(Y_, PP, MN_ + 1536, ZP, ZP, PP);   // D seed (pre-identity)
    kdiag<<<1, 64>>>(MN_);

    // x split early (independent)
    splitP(x, XCW, xh, xl, XCW, MROW, XCW);

    // ---- seed planes: A = [M; V_0=N] (one split covers both), B = [M | Y_0=D] ----
    splitP(MN_, ZP, Ah_, Al_, AK, MNR, ZP);
    splitP(MN_, ZP, Bh_, Bl_, CW, ZP, ZP);
    splitP(Y_, PP, Bh_ + ZP, Bl_ + ZP, CW, ZP, PP);

    // ---- merged doubling rounds: 1 plane-GEMM + 1 redistribute per round ----
    for (int d = 0; d < 5; ++d) {
        const int w = 32 << d, r = 64 << d;
        gemmF(Ah_, Al_, AK, Bh_, Bl_, CW, nullptr, 0,
              ZP + r, ZP + w, ZP, 0, CRh_, CRl_, CW, 0);
        int total = ZP*ZP + r*ZP + ZP*w;
        kround<<<L1D(total)>>>(CRh_, CRl_, Ah_, Al_, Bh_, Bl_, r, w);
    }
    // CR holds M^32 planes; A rows 1600.. = V stack; B cols 1600.. = Y stack

    // ---- chain B = [Ystack | M32] ----
    kwcat<<<L1D(ZP*CW)>>>(Wh_, Wl_, Bh_, Bl_, CRh_, CRl_);

    // ---- NY = N @ Ystack (plane GEMM); Hcat planes ----
    gemmF(Ah_ + (size_t)ZP*AK, Al_ + (size_t)ZP*AK, AK,
          Bh_ + ZP, Bl_ + ZP, CW, NY_, YW, 64, YW, ZP, 0);
    khbuild_bf<<<L1D(XCW*YW)>>>(hh, hl, NY_, Nrow);
    kqrev_bf<<<L1D(XCW*ZP)>>>(hh, hl, Ah_ + (size_t)ZP*AK, Al_ + (size_t)ZP*AK);

    // ---- giant x-driven GEMM: XC = X * Hcat (8192 x 2624 x 2048) ----
    gemmF(xh, xl, XCW, hh, hl, CW, XC_, CW, MROW, CW, XCW, 0);

    // ---- serial z-chain (fused z-plane epilogue) ----
    kzplanes<<<L1D(BB*ZP)>>>(z0h, z0l);
    for (int c = 0; c < NCH; ++c) {
        const bf16* ah = (c & 1) ? z1h : z0h;
        const bf16* al = (c & 1) ? z1l : z0l;
        bf16* oh = (c & 1) ? z0h : z1h;
        bf16* ol = (c & 1) ? z0l : z1l;
        gemmF(ah, al, ZP, Wh_, Wl_, CW, XC_ + (size_t)c * CW, NCH * CW,
              BB, CW, ZP, 1, oh, ol, ZP, YW);
    }

    // ---- scatter y-part to output ----
    kout<<<L1D(BB*TT*PP)>>>(out, XC_);
}

// round 17
// speedup vs baseline: 1.4185x; 1.0205x over previous
#include <cuda_runtime.h>
#include <cuda_bf16.h>
#include <cstdint>
#include <cstddef>

// Problem constants
#define BB 512
#define TT 512
#define FF 64
#define PP 32
#define UU 512

// Affine-state formulation
#define ZP   1600
#define HOM  1568
#define CH   32
#define NCH  (TT/CH)
#define XCW  (CH*FF)       // 2048
#define YW   (CH*PP)       // 1024
#define MROW (BB*NCH)      // 8192
#define CW   (YW+ZP)       // 2624
#define AK   1600          // A-plane pitch
#define ARR  3648          // A-plane rows (1600 power + 2048 V stack)
#define MNR  1664          // merged [M; N] rows

typedef unsigned long long u64;
typedef __nv_bfloat16 bf16;

// ---------------- fp32 scratch ----------------
__device__ __align__(256) float gMN[(size_t)MNR*ZP];   // rows 0-1599: M, 1600-1663: N
__device__ __align__(256) float gT1[(size_t)MNR*UU];
__device__ __align__(256) float gY[ZP*PP];
__device__ __align__(256) float gNY[64*YW];
__device__ __align__(256) float gXC[(size_t)MROW*ZP];  // z-accumulator only (X*Q)

// ---------------- bf16 planes ----------------
__device__ __align__(256) bf16 gAh[(size_t)ARR*AK], gAl[(size_t)ARR*AK];   // [power; V stack]
__device__ __align__(256) bf16 gBh[(size_t)ZP*CW],  gBl[(size_t)ZP*CW];    // [power | Y stack]
__device__ __align__(256) bf16 gCRh[(size_t)2624*CW], gCRl[(size_t)2624*CW]; // round output
__device__ __align__(256) bf16 gWh[(size_t)ZP*CW],  gWl[(size_t)ZP*CW];    // chain B = [Y | M32]
__device__ __align__(256) bf16 ghh[(size_t)XCW*CW], ghl[(size_t)XCW*CW];   // Hcat planes
__device__ __align__(256) bf16 gxh[(size_t)MROW*XCW], gxl[(size_t)MROW*XCW];
__device__ __align__(256) bf16 gz0h[BB*ZP], gz0l[BB*ZP], gz1h[BB*ZP], gz1l[BB*ZP];

// ================= PTX helpers =================
__device__ __forceinline__ uint32_t bfpack(float x, float y) {  // lo=x, hi=y
    uint32_t r;
    asm("cvt.rn.bf16x2.f32 %0, %1, %2;" : "=r"(r) : "f"(y), "f"(x));
    return r;
}
__device__ __forceinline__ void ldsm4(uint32_t& r0, uint32_t& r1,
                                      uint32_t& r2, uint32_t& r3, uint32_t a) {
    asm volatile("ldmatrix.sync.aligned.m8n8.x4.shared.b16 {%0,%1,%2,%3}, [%4];"
                 : "=r"(r0), "=r"(r1), "=r"(r2), "=r"(r3) : "r"(a));
}
__device__ __forceinline__ void ldsm4t(uint32_t& r0, uint32_t& r1,
                                       uint32_t& r2, uint32_t& r3, uint32_t a) {
    asm volatile("ldmatrix.sync.aligned.m8n8.x4.trans.shared.b16 {%0,%1,%2,%3}, [%4];"
                 : "=r"(r0), "=r"(r1), "=r"(r2), "=r"(r3) : "r"(a));
}
__device__ __forceinline__ void mma16816(float* c, const uint32_t* a, const uint32_t* b) {
    asm volatile("mma.sync.aligned.m16n8k16.row.col.f32.bf16.bf16.f32 "
                 "{%0,%1,%2,%3}, {%4,%5,%6,%7}, {%8,%9}, {%0,%1,%2,%3};"
                 : "+f"(c[0]), "+f"(c[1]), "+f"(c[2]), "+f"(c[3])
                 : "r"(a[0]), "r"(a[1]), "r"(a[2]), "r"(a[3]),
                   "r"(b[0]), "r"(b[1]));
}
__device__ __forceinline__ void cpa16(uint32_t d, const void* g, int bytes) {
    asm volatile("cp.async.cg.shared.global [%0], [%1], 16, %2;"
                 :: "r"(d), "l"(g), "r"(bytes));
}
__device__ __forceinline__ void cpcommit() { asm volatile("cp.async.commit_group;"); }
template<int n> __device__ __forceinline__ void cpwait() {
    asm volatile("cp.async.wait_group %0;" :: "n"(n));
}

// ================= pre-split bf16 GEMM (2 CTAs/SM) =================
#define S2   2
#define AROW 80
#define BROW 272
#define A_T  (128*AROW)
#define B_T  (32*BROW)
#define SLOT (2*A_T + 2*B_T)
#define GS2  (S2*SLOT)              // 75776 B -> 2 CTAs/SM

__device__ __forceinline__ void issue_stage(
    uint32_t sb, int s, int m0, int n0, int M, int N, int lda, int ldb,
    const bf16* __restrict__ Ah, const bf16* __restrict__ Al,
    const bf16* __restrict__ Bh, const bf16* __restrict__ Bl, int tid)
{
    const int k0 = s * 32;
    const uint32_t sl = sb + (uint32_t)((s % S2) * SLOT);
#pragma unroll
    for (int q = 0; q < 2; ++q) {
        int c = tid + q * 256;
        int m = c >> 2, kc = c & 3;
        int row = m0 + m;
        int bytes = (row < M) ? 16 : 0;
        int rs = bytes ? row : 0;
        const bf16* s1 = Ah + (size_t)rs * lda + k0 + kc * 8;
        const bf16* s2 = Al + (size_t)rs * lda + k0 + kc * 8;
        cpa16(sl + m * AROW + kc * 16, s1, bytes);
        cpa16(sl + A_T + m * AROW + kc * 16, s2, bytes);
    }
#pragma unroll
    for (int q = 0; q < 2; ++q) {
        int c = tid + q * 256;
        int k = c >> 4, nc = c & 15;
        int col = n0 + nc * 8;
        int bytes = (col < N) ? 16 : 0;
        int cs = bytes ? col : 0;
        const bf16* s1 = Bh + (size_t)(k0 + k) * ldb + cs;
        const bf16* s2 = Bl + (size_t)(k0 + k) * ldb + cs;
        cpa16(sl + 2 * A_T + k * BROW + nc * 16, s1, bytes);
        cpa16(sl + 2 * A_T + B_T + k * BROW + nc * 16, s2, bytes);
    }
    cpcommit();
}

// mode 0: C fp32 (optional accum) + optional planes (cols >= ocol0, shifted)
// mode 1 (x-GEMM): rows m = b*16+c. y cols -> outp[b][c*32.. ] direct;
//                  z cols -> zbuf[m*ZP + cc-YW]. Triangular K-clip on y tiles.
// mode 2 (chain):  rows = b. y cols -> outp accum at b*16384 + cidx*1024 + cc;
//                  z cols -> acc += zbuf[(b*16+cidx)*ZP + cc-YW], planes only.
__global__ void __launch_bounds__(256, 2) gemm_bf(
    const bf16* __restrict__ Ah, const bf16* __restrict__ Al, int lda,
    const bf16* __restrict__ Bh, const bf16* __restrict__ Bl, int ldb,
    float* __restrict__ C, int ldc, int M, int N, int K, int accum,
    bf16* __restrict__ oh, bf16* __restrict__ ol, int opitch, int ocol0,
    int mode, int cidx, float* __restrict__ outp, float* __restrict__ zbuf)
{
    extern __shared__ __align__(16) char smem[];
    const uint32_t sb = (uint32_t)__cvta_generic_to_shared(smem);
    const int tid  = threadIdx.x;
    const int wid  = tid >> 5;
    const int lane = tid & 31;
    const int m0 = blockIdx.y * 128;
    const int n0 = blockIdx.x * 128;
    const int wm = (wid >> 2) * 64;
    const int wn = (wid & 3) * 32;

    int Keff = K;
    if (mode == 1 && n0 + 128 <= YW) {       // pure y tile: block-triangular Hy
        int jmax = (n0 + 127) >> 5;
        Keff = (jmax + 1) * 64;
        if (Keff > K) Keff = K;
    }

    float acc[4][4][4];
#pragma unroll
    for (int mi = 0; mi < 4; ++mi)
#pragma unroll
        for (int ni = 0; ni < 4; ++ni)
#pragma unroll
            for (int r = 0; r < 4; ++r) acc[mi][ni][r] = 0.f;

    const int nk = Keff / 32;
    const int pro = (S2 - 1 < nk) ? S2 - 1 : nk;
    for (int s = 0; s < pro; ++s)
        issue_stage(sb, s, m0, n0, M, N, lda, ldb, Ah, Al, Bh, Bl, tid);

    const uint32_t a_lrow = (uint32_t)(lane & 15);
    const uint32_t a_lchk = (uint32_t)(lane >> 4);
    const uint32_t b_krow = (uint32_t)(lane & 15);
    const uint32_t b_ncol = (uint32_t)((lane >> 4) * 8);

    for (int s = 0; s < nk; ++s) {
        cpwait<S2 - 2>();
        __syncthreads();
        if (s + S2 - 1 < nk)
            issue_stage(sb, s + S2 - 1, m0, n0, M, N, lda, ldb, Ah, Al, Bh, Bl, tid);

        const uint32_t base = sb + (uint32_t)((s % S2) * SLOT);
#pragma unroll
        for (int kk = 0; kk < 2; ++kk) {
            uint32_t ah[4][4], al[4][4], bh[4][2], bl[4][2];
#pragma unroll
            for (int mi = 0; mi < 4; ++mi) {
                uint32_t off = (uint32_t)(wm + mi * 16 + a_lrow) * AROW
                             + (uint32_t)(kk * 2 + a_lchk) * 16;
                ldsm4(ah[mi][0], ah[mi][1], ah[mi][2], ah[mi][3], base + off);
                ldsm4(al[mi][0], al[mi][1], al[mi][2], al[mi][3], base + A_T + off);
            }
#pragma unroll
            for (int h = 0; h < 2; ++h) {
                uint32_t off = (uint32_t)(kk * 16 + b_krow) * BROW
                             + (uint32_t)(wn + h * 16 + b_ncol) * 2;
                uint32_t t0, t1, t2, t3;
                ldsm4t(t0, t1, t2, t3, base + 2 * A_T + off);
                bh[2*h][0] = t0; bh[2*h][1] = t1; bh[2*h+1][0] = t2; bh[2*h+1][1] = t3;
                ldsm4t(t0, t1, t2, t3, base + 2 * A_T + B_T + off);
                bl[2*h][0] = t0; bl[2*h][1] = t1; bl[2*h+1][0] = t2; bl[2*h+1][1] = t3;
            }
#pragma unroll
            for (int mi = 0; mi < 4; ++mi)
#pragma unroll
                for (int ni = 0; ni < 4; ++ni) {
                    mma16816(acc[mi][ni], ah[mi], bh[ni]);
                    mma16816(acc[mi][ni], ah[mi], bl[ni]);
                    mma16816(acc[mi][ni], al[mi], bh[ni]);
                }
        }
    }

#pragma unroll
    for (int mi = 0; mi < 4; ++mi) {
        int r0 = m0 + wm + mi * 16 + (lane >> 2);
        int r1 = r0 + 8;
#pragma unroll
        for (int ni = 0; ni < 4; ++ni) {
            int cc = n0 + wn + ni * 8 + (lane & 3) * 2;
            if (cc < N) {
#pragma unroll
                for (int hh2 = 0; hh2 < 2; ++hh2) {
                    int row = hh2 ? r1 : r0;
                    if (row < M) {
                        float vx = acc[mi][ni][hh2 * 2];
                        float vy = acc[mi][ni][hh2 * 2 + 1];
                        if (mode == 1) {
                            if (cc < YW) {
                                float2* p = reinterpret_cast<float2*>(
                                    outp + ((size_t)(row >> 4)) * 16384
                                         + (size_t)(row & 15) * 1024 + cc);
                                *p = make_float2(vx, vy);
                            } else {
                                float2* p = reinterpret_cast<float2*>(
                                    zbuf + (size_t)row * ZP + (cc - YW));
                                *p = make_float2(vx, vy);
                            }
                        } else if (mode == 2) {
                            if (cc < YW) {
                                float2* p = reinterpret_cast<float2*>(
                                    outp + (size_t)row * 16384
                                         + (size_t)cidx * 1024 + cc);
                                float2 v = *p;
                                v.x += vx; v.y += vy;
                                *p = v;
                            } else {
                                float2 zv = *reinterpret_cast<const float2*>(
                                    zbuf + ((size_t)(row * NCH + cidx)) * ZP + (cc - YW));
                                vx += zv.x; vy += zv.y;
                                if (oh) {
                                    float hx = __bfloat162float(__float2bfloat16(vx));
                                    float hy = __bfloat162float(__float2bfloat16(vy));
                                    size_t oidx = (size_t)row * opitch + (cc - YW);
                                    *reinterpret_cast<uint32_t*>(oh + oidx) = bfpack(vx, vy);
                                    *reinterpret_cast<uint32_t*>(ol + oidx) =
                                        bfpack(vx - hx, vy - hy);
                                }
                            }
                        } else {
                            if (C) {
                                float2* p = reinterpret_cast<float2*>(
                                    &C[(size_t)row * ldc + cc]);
                                if (accum) { float2 v = *p; vx += v.x; vy += v.y; }
                                *p = make_float2(vx, vy);
                            }
                            if (oh && cc >= ocol0) {
                                float hx = __bfloat162float(__float2bfloat16(vx));
                                float hy = __bfloat162float(__float2bfloat16(vy));
                                size_t oidx = (size_t)row * opitch + (cc - ocol0);
                                *reinterpret_cast<uint32_t*>(oh + oidx) = bfpack(vx, vy);
                                *reinterpret_cast<uint32_t*>(ol + oidx) =
                                    bfpack(vx - hx, vy - hy);
                            }
                        }
                    }
                }
            }
        }
    }
}

// ================= slow path: fp32-input GEMM (small builds) ==
#define TBM 128
#define TBN 128
#define TBK 32
#define ROWB 80
#define TILEB (128*ROWB)
#define BUFB (4*TILEB)
#define GSMEM (2*BUFB)

__device__ __forceinline__ void ldg_tiles(
    const float* __restrict__ A, int lda, int M, int m0,
    const float* __restrict__ B, int ldb, int N, int n0,
    int k0, int smr, int kh, float4 ra[4], float rb[16])
{
    const float4 z4 = make_float4(0.f, 0.f, 0.f, 0.f);
    if (m0 + smr < M) {
        const float* ap = A + (size_t)(m0 + smr) * lda + k0 + kh;
#pragma unroll
        for (int j = 0; j < 4; ++j)
            ra[j] = *reinterpret_cast<const float4*>(ap + 4 * j);
    } else {
#pragma unroll
        for (int j = 0; j < 4; ++j) ra[j] = z4;
    }
    if (n0 + smr < N) {
        const float* bp = B + (size_t)(k0 + kh) * ldb + (n0 + smr);
#pragma unroll
        for (int j = 0; j < 16; ++j) rb[j] = bp[(size_t)j * ldb];
    } else {
#pragma unroll
        for (int j = 0; j < 16; ++j) rb[j] = 0.f;
    }
}
__device__ __forceinline__ void split8(const float* v, uint32_t* hw, uint32_t* lw) {
#pragma unroll
    for (int j = 0; j < 8; ++j) {
        float x = v[2 * j], y = v[2 * j + 1];
        float hx = __bfloat162float(__float2bfloat16(x));
        float hy = __bfloat162float(__float2bfloat16(y));
        hw[j] = bfpack(x, y);
        lw[j] = bfpack(x - hx, y - hy);
    }
}
__device__ __forceinline__ void sts_tiles(char* smem, int buf, int smr, int kh,
                                          const float4 ra[4], const float rb[16])
{
    char* base = smem + buf * BUFB;
    uint32_t hw[8], lw[8];
    float av[16];
#pragma unroll
    for (int j = 0; j < 4; ++j) {
        av[4*j] = ra[j].x; av[4*j+1] = ra[j].y; av[4*j+2] = ra[j].z; av[4*j+3] = ra[j].w;
    }
    split8(av, hw, lw);
    {
        char* d = base + smr * ROWB + kh * 2;
        *reinterpret_cast<uint4*>(d)      = make_uint4(hw[0], hw[1], hw[2], hw[3]);
        *reinterpret_cast<uint4*>(d + 16) = make_uint4(hw[4], hw[5], hw[6], hw[7]);
        char* d2 = d + TILEB;
        *reinterpret_cast<uint4*>(d2)      = make_uint4(lw[0], lw[1], lw[2], lw[3]);
        *reinterpret_cast<uint4*>(d2 + 16) = make_uint4(lw[4], lw[5], lw[6], lw[7]);
    }
    split8(rb, hw, lw);
    {
        char* d = base + 2 * TILEB + smr * ROWB + kh * 2;
        *reinterpret_cast<uint4*>(d)      = make_uint4(hw[0], hw[1], hw[2], hw[3]);
        *reinterpret_cast<uint4*>(d + 16) = make_uint4(hw[4], hw[5], hw[6], hw[7]);
        char* d2 = d + TILEB;
        *reinterpret_cast<uint4*>(d2)      = make_uint4(lw[0], lw[1], lw[2], lw[3]);
        *reinterpret_cast<uint4*>(d2 + 16) = make_uint4(lw[4], lw[5], lw[6], lw[7]);
    }
}

__global__ void __launch_bounds__(256, 1) tcgemm_k(
    const float* __restrict__ A, int lda,
    const float* __restrict__ B, int ldb,
    float* __restrict__ C, int ldc,
    int M, int N, int K, int accum)
{
    extern __shared__ __align__(16) char smem[];
    const uint32_t sb = (uint32_t)__cvta_generic_to_shared(smem);
    const int tid  = threadIdx.x;
    const int wid  = tid >> 5;
    const int lane = tid & 31;
    const int m0 = blockIdx.y * TBM;
    const int n0 = blockIdx.x * TBN;
    const int wm = (wid >> 2) * 64;
    const int wn = (wid & 3) * 32;
    const int smr = tid >> 1;
    const int kh  = (tid & 1) * 16;

    float acc[4][4][4];
#pragma unroll
    for (int mi = 0; mi < 4; ++mi)
#pragma unroll
        for (int ni = 0; ni < 4; ++ni)
#pragma unroll
            for (int r = 0; r < 4; ++r) acc[mi][ni][r] = 0.f;

    const uint32_t a_lrow = (uint32_t)(lane & 15);
    const uint32_t a_lchk = (uint32_t)(lane >> 4);
    const uint32_t b_lrow = (uint32_t)(((lane >> 4) << 3) + (lane & 7));
    const uint32_t b_lchk = (uint32_t)((lane >> 3) & 1);

    const int nk = K / TBK;
    float4 ra[4]; float rb[16];
    ldg_tiles(A, lda, M, m0, B, ldb, N, n0, 0, smr, kh, ra, rb);
    sts_tiles(smem, 0, smr, kh, ra, rb);
    __syncthreads();

    for (int s = 0; s < nk; ++s) {
        if (s + 1 < nk)
            ldg_tiles(A, lda, M, m0, B, ldb, N, n0, (s + 1) * TBK, smr, kh, ra, rb);
        const uint32_t base = sb + (uint32_t)((s & 1) * BUFB);
#pragma unroll
        for (int kk = 0; kk < 2; ++kk) {
            uint32_t ah[4][4], al[4][4], bh[4][2], bl[4][2];
#pragma unroll
            for (int mi = 0; mi < 4; ++mi) {
                uint32_t off = (uint32_t)(wm + mi * 16 + a_lrow) * ROWB
                             + (uint32_t)(kk * 2 + a_lchk) * 16;
                ldsm4(ah[mi][0], ah[mi][1], ah[mi][2], ah[mi][3], base + off);
                ldsm4(al[mi][0], al[mi][1], al[mi][2], al[mi][3], base + TILEB + off);
            }
#pragma unroll
            for (int h = 0; h < 2; ++h) {
                uint32_t off = (uint32_t)(wn + h * 16 + b_lrow) * ROWB
                             + (uint32_t)(kk * 2 + b_lchk) * 16;
                uint32_t t0, t1, t2, t3;
                ldsm4(t0, t1, t2, t3, base + 2 * TILEB + off);
                bh[2*h][0] = t0; bh[2*h][1] = t1; bh[2*h+1][0] = t2; bh[2*h+1][1] = t3;
                ldsm4(t0, t1, t2, t3, base + 3 * TILEB + off);
                bl[2*h][0] = t0; bl[2*h][1] = t1; bl[2*h+1][0] = t2; bl[2*h+1][1] = t3;
            }
#pragma unroll
            for (int mi = 0; mi < 4; ++mi)
#pragma unroll
                for (int ni = 0; ni < 4; ++ni) {
                    mma16816(acc[mi][ni], ah[mi], bh[ni]);
                    mma16816(acc[mi][ni], ah[mi], bl[ni]);
                    mma16816(acc[mi][ni], al[mi], bh[ni]);
                }
        }
        __syncthreads();
        if (s + 1 < nk) {
            sts_tiles(smem, (s + 1) & 1, smr, kh, ra, rb);
            __syncthreads();
        }
    }
#pragma unroll
    for (int mi = 0; mi < 4; ++mi) {
        int r0 = m0 + wm + mi * 16 + (lane >> 2);
        int r1 = r0 + 8;
#pragma unroll
        for (int ni = 0; ni < 4; ++ni) {
            int cc = n0 + wn + ni * 8 + (lane & 3) * 2;
            if (cc < N) {
                if (r0 < M) {
                    float2* p = reinterpret_cast<float2*>(&C[(size_t)r0 * ldc + cc]);
                    float2 v = accum ? *p : make_float2(0.f, 0.f);
                    v.x += acc[mi][ni][0]; v.y += acc[mi][ni][1];
                    *p = v;
                }
                if (r1 < M) {
                    float2* p = reinterpret_cast<float2*>(&C[(size_t)r1 * ldc + cc]);
                    float2 v = accum ? *p : make_float2(0.f, 0.f);
                    v.x += acc[mi][ni][2]; v.y += acc[mi][ni][3];
                    *p = v;
                }
            }
        }
    }
}

// ---------------- small helper kernels ----------------
__global__ void kzero(float* p, int n) {
    int i = blockIdx.x * blockDim.x + threadIdx.x;
    if (i < n) p[i] = 0.f;
}
__global__ void kcopy(float* dst, int ldd, const float* src, int lds, int rows, int cols) {
    int i = blockIdx.x * blockDim.x + threadIdx.x;
    if (i >= rows * cols) return;
    int r = i / cols, c = i - r * cols;
    dst[(size_t)r * ldd + c] = src[(size_t)r * lds + c];
}
__global__ void kaddb(float* dst, int ldd, const float* src, int lds, int rows, int cols) {
    int i = blockIdx.x * blockDim.x + threadIdx.x;
    if (i >= rows * cols) return;
    int r = i / cols, c = i - r * cols;
    dst[(size_t)r * ldd + c] += src[(size_t)r * lds + c];
}
__global__ void kvadd2(float* dst, const float* a, const float* b, int n) {
    int i = blockIdx.x * blockDim.x + threadIdx.x;
    if (i < n) dst[i] = a[i] + b[i];
}
__global__ void kvaddrow(float* dst, const float* src, int n) {
    int i = blockIdx.x * blockDim.x + threadIdx.x;
    if (i < n) dst[i] += src[i];
}
__global__ void kdiag(float* M) {
    int i = threadIdx.x;
    if (i < PP) M[(size_t)(1536 + i) * ZP + 1536 + i] += 1.f;
    if (i == PP) M[(size_t)HOM * ZP + HOM] += 1.f;
}
// Redistribute round output planes: power -> A & B, V append -> A, Y append -> B
__global__ void kround(const bf16* __restrict__ crh, const bf16* __restrict__ crl,
                       bf16* __restrict__ ah, bf16* __restrict__ al,
                       bf16* __restrict__ bh, bf16* __restrict__ bl,
                       int r, int w)
{
    const int P2 = ZP * ZP;
    int total = P2 + r * ZP + ZP * w;
    int i = blockIdx.x * blockDim.x + threadIdx.x;
    if (i >= total) return;
    if (i < P2) {
        int row = i / ZP, col = i - row * ZP;
        size_t s = (size_t)row * CW + col;
        bf16 h = crh[s], lo = crl[s];
        size_t da = (size_t)row * AK + col;
        ah[da] = h; al[da] = lo;
        bh[s] = h; bl[s] = lo;          // B pitch == CW
    } else if (i < P2 + r * ZP) {
        int j = i - P2;
        int row = j / ZP, col = j - row * ZP;
        size_t s = (size_t)(ZP + row) * CW + col;
        size_t d = (size_t)(ZP + r + row) * AK + col;
        ah[d] = crh[s]; al[d] = crl[s];
    } else {
        int j = i - P2 - r * ZP;
        int row = j / w, col = j - row * w;
        size_t s = (size_t)row * CW + ZP + col;
        size_t d = (size_t)row * CW + ZP + w + col;
        bh[d] = crh[s]; bl[d] = crl[s];
    }
}
// chain B = [Ystack | M32] planes
__global__ void kwcat(bf16* __restrict__ wh, bf16* __restrict__ wl,
                      const bf16* __restrict__ bh, const bf16* __restrict__ bl,
                      const bf16* __restrict__ crh, const bf16* __restrict__ crl)
{
    int i = blockIdx.x * blockDim.x + threadIdx.x;
    if (i >= ZP * CW) return;
    int row = i / CW, col = i - row * CW;
    bf16 h, lo;
    if (col < YW) { size_t s = (size_t)row * CW + ZP + col; h = bh[s]; lo = bl[s]; }
    else          { size_t s = (size_t)row * CW + (col - YW); h = crh[s]; lo = crl[s]; }
    wh[i] = h; wl[i] = lo;
}
__global__ void khbuild_bf(bf16* hh, bf16* hl, const float* NY, const float* Nm) {
    int idx = blockIdx.x * blockDim.x + threadIdx.x;
    if (idx >= XCW * YW) return;
    int row = idx >> 10, col = idx & 1023;
    int i = row >> 6, f = row & 63;
    int j = col >> 5, p = col & 31;
    float v = 0.f;
    if (j == i)      v = Nm[(size_t)f * ZP + 1536 + p];
    else if (j > i)  v = NY[(size_t)f * YW + (j - i - 1) * PP + p];
    bf16 h = __float2bfloat16(v);
    hh[(size_t)row * CW + col] = h;
    hl[(size_t)row * CW + col] = __float2bfloat16(v - __bfloat162float(h));
}
// Q plane region from V planes (A buffer rows 1600.., pitch AK)
__global__ void kqrev_bf(bf16* hh, bf16* hl, const bf16* vh, const bf16* vl) {
    int idx = blockIdx.x * blockDim.x + threadIdx.x;
    if (idx >= XCW * ZP) return;
    int row = idx / ZP, col = idx - row * ZP;
    int i = row >> 6, f = row & 63;
    size_t src = (size_t)((31 - i) * 64 + f) * AK + col;
    hh[(size_t)row * CW + YW + col] = vh[src];
    hl[(size_t)row * CW + YW + col] = vl[src];
}
__global__ void ksplitP(const float* __restrict__ src, int lds,
                        bf16* __restrict__ hi, bf16* __restrict__ lo, int ldd,
                        int rows, int cols) {
    int i = blockIdx.x * blockDim.x + threadIdx.x;
    if (i >= rows * cols) return;
    int r = i / cols, c = i - r * cols;
    float v = src[(size_t)r * lds + c];
    bf16 h = __float2bfloat16(v);
    hi[(size_t)r * ldd + c] = h;
    lo[(size_t)r * ldd + c] = __float2bfloat16(v - __bfloat162float(h));
}
__global__ void kzplanes(bf16* h, bf16* l) {
    int i = blockIdx.x * blockDim.x + threadIdx.x;
    if (i >= BB * ZP) return;
    int c = i % ZP;
    h[i] = __float2bfloat16((c == HOM) ? 1.f : 0.f);
    l[i] = __float2bfloat16(0.f);
}

// ---------------- host ----------------
static void gemm(const float* A, int lda, const float* B, int ldb,
                 float* C, int ldc, int M, int N, int K, int acc)
{
    dim3 g((unsigned)((N + TBN - 1) / TBN), (unsigned)((M + TBM - 1) / TBM));
    tcgemm_k<<<g, 256, GSMEM>>>(A, lda, B, ldb, C, ldc, M, N, K, acc);
}
static void gemmF(const bf16* Ah, const bf16* Al, int lda,
                  const bf16* Bh, const bf16* Bl, int ldb,
                  float* C, int ldc, int M, int N, int K, int acc,
                  bf16* oh = nullptr, bf16* ol = nullptr, int opitch = 0, int ocol0 = 0,
                  int mode = 0, int cidx = 0, float* outp = nullptr, float* zbuf = nullptr)
{
    dim3 g((unsigned)((N + 127) / 128), (unsigned)((M + 127) / 128));
    gemm_bf<<<g, 256, GS2>>>(Ah, Al, lda, Bh, Bl, ldb, C, ldc, M, N, K, acc,
                             oh, ol, opitch, ocol0, mode, cidx, outp, zbuf);
}
#define L1D(n) (((n) + 255) / 256), 256
static void splitP(const float* src, int lds, bf16* hi, bf16* lo, int ldd,
                   int rows, int cols) {
    ksplitP<<<L1D(rows * cols)>>>(src, lds, hi, lo, ldd, rows, cols);
}

extern "C" void kernel_launch(void* const* d_in, const int* in_sizes, int n_in,
                              void* d_out, int out_size)
{
    const float* x    = (const float*)d_in[0];
    const float* WA   = (const float*)d_in[1];
    const float* bA   = (const float*)d_in[2];
    const float* WB0  = (const float*)d_in[3];
    const float* bB0  = (const float*)d_in[4];
    const float* WBr  = (const float*)d_in[5];
    const float* bBr  = (const float*)d_in[6];
    const float* WC   = (const float*)d_in[7];
    const float* bC   = (const float*)d_in[8];
    const float* Wout = (const float*)d_in[9];
    const float* bout = (const float*)d_in[10];
    float* out = (float*)d_out;

    static int attr_done = 0;
    if (!attr_done) {
        cudaFuncSetAttribute(tcgemm_k, cudaFuncAttributeMaxDynamicSharedMemorySize, GSMEM);
        cudaFuncSetAttribute(gemm_bf,  cudaFuncAttributeMaxDynamicSharedMemorySize, GS2);
        attr_done = 1;
    }

    float *MN_, *T1_, *Y_, *NY_, *XC_;
    cudaGetSymbolAddress((void**)&MN_, gMN);  cudaGetSymbolAddress((void**)&T1_, gT1);
    cudaGetSymbolAddress((void**)&Y_,  gY);   cudaGetSymbolAddress((void**)&NY_, gNY);
    cudaGetSymbolAddress((void**)&XC_, gXC);

    bf16 *Ah_, *Al_, *Bh_, *Bl_, *CRh_, *CRl_, *Wh_, *Wl_, *hh, *hl, *xh, *xl;
    bf16 *z0h, *z0l, *z1h, *z1l;
    cudaGetSymbolAddress((void**)&Ah_,  gAh);  cudaGetSymbolAddress((void**)&Al_,  gAl);
    cudaGetSymbolAddress((void**)&Bh_,  gBh);  cudaGetSymbolAddress((void**)&Bl_,  gBl);
    cudaGetSymbolAddress((void**)&CRh_, gCRh); cudaGetSymbolAddress((void**)&CRl_, gCRl);
    cudaGetSymbolAddress((void**)&Wh_,  gWh);  cudaGetSymbolAddress((void**)&Wl_,  gWl);
    cudaGetSymbolAddress((void**)&hh,   ghh);  cudaGetSymbolAddress((void**)&hl,   ghl);
    cudaGetSymbolAddress((void**)&xh,   gxh);  cudaGetSymbolAddress((void**)&xl,   gxl);
    cudaGetSymbolAddress((void**)&z0h,  gz0h); cudaGetSymbolAddress((void**)&z0l,  gz0l);
    cudaGetSymbolAddress((void**)&z1h,  gz1h); cudaGetSymbolAddress((void**)&z1l,  gz1l);

    const int W2 = UU * UU;
    float* Nrow = MN_ + (size_t)1600 * ZP;   // N block (rows 1600-1663)

    // ---- build merged MN = [M; N] (fp32 path) ----
    kzero<<<L1D(MNR*ZP)>>>(MN_, MNR*ZP);

    kcopy<<<L1D(UU*UU)>>>(MN_,                   ZP, WA,          UU, UU, UU);
    kcopy<<<L1D(PP*UU)>>>(MN_ + (size_t)1536*ZP, ZP, WB0 + 64*UU, UU, PP, UU);
    kvadd2<<<L1D(UU)>>>(MN_ + (size_t)HOM*ZP, bA, bB0, UU);
    kcopy<<<L1D(64*UU)>>>(Nrow,                  ZP, WB0,         UU, 64, UU);

    for (int l = 0; l < 2; ++l) {
        gemm(MN_ + l * 512, ZP, WC + (size_t)l * W2, UU, T1_, UU, MNR, UU, UU, 0);
        kvaddrow<<<L1D(UU)>>>(T1_ + (size_t)HOM*UU, bC + l*UU, UU);
        gemm(T1_, UU, WBr + (size_t)l * W2, UU, MN_ + (l + 1) * 512, ZP, MNR, UU, UU, 0);
        kaddb<<<L1D(UU*UU)>>>(MN_ + (size_t)(l+1)*512*ZP + (l+1)*512, ZP,
                              WA + (size_t)(l+1)*W2, UU, UU, UU);
        kvaddrow<<<L1D(UU)>>>(MN_ + (size_t)HOM*ZP + (l+1)*512, bA + (l+1)*UU, UU);
        kvaddrow<<<L1D(UU)>>>(MN_ + (size_t)HOM*ZP + (l+1)*512, bBr + l*UU, UU);
    }

    gemm(MN_ + 1024, ZP, WC + (size_t)2*W2, UU, T1_, UU, MNR, UU, UU, 0);
    kvaddrow<<<L1D(UU)>>>(T1_ + (size_t)HOM*UU, bC + 2*UU, UU);
    gemm(T1_, UU, Wout, PP, MN_ + 1536, ZP, MNR, PP, UU, 0);
    kvaddrow<<<L1D(PP)>>>(MN_ + (size_t)HOM*ZP + 1536, bout, PP);
    kcopy<<<L1D(ZP*PP)>>>(Y_, PP, MN_ + 1536, ZP, ZP, PP);   // D seed (pre-identity)
    kdiag<<<1, 64>>>(MN_);

    // x split early (independent)
    splitP(x, XCW, xh, xl, XCW, MROW, XCW);

    // ---- seed planes: A = [M; V_0=N] (single split), B = [M | Y_0=D] ----
    splitP(MN_, ZP, Ah_, Al_, AK, MNR, ZP);
    splitP(MN_, ZP, Bh_, Bl_, CW, ZP, ZP);
    splitP(Y_, PP, Bh_ + ZP, Bl_ + ZP, CW, ZP, PP);

    // ---- merged doubling rounds: 1 plane-GEMM + 1 redistribute per round ----
    for (int d = 0; d < 5; ++d) {
        const int w = 32 << d, r = 64 << d;
        gemmF(Ah_, Al_, AK, Bh_, Bl_, CW, nullptr, 0,
              ZP + r, ZP + w, ZP, 0, CRh_, CRl_, CW, 0);
        int total = ZP*ZP + r*ZP + ZP*w;
        kround<<<L1D(total)>>>(CRh_, CRl_, Ah_, Al_, Bh_, Bl_, r, w);
    }
    // CR holds M^32 planes; A rows 1600.. = V stack; B cols 1600.. = Y stack

    // ---- chain B = [Ystack | M32] ----
    kwcat<<<L1D(ZP*CW)>>>(Wh_, Wl_, Bh_, Bl_, CRh_, CRl_);

    // ---- NY = N @ Ystack (plane GEMM); Hcat planes ----
    gemmF(Ah_ + (size_t)ZP*AK, Al_ + (size_t)ZP*AK, AK,
          Bh_ + ZP, Bl_ + ZP, CW, NY_, YW, 64, YW, ZP, 0);
    khbuild_bf<<<L1D(XCW*YW)>>>(hh, hl, NY_, Nrow);
    kqrev_bf<<<L1D(XCW*ZP)>>>(hh, hl, Ah_ + (size_t)ZP*AK, Al_ + (size_t)ZP*AK);

    // ---- giant x-driven GEMM (mode 1): y -> out direct, z -> XC; tri-clipped ----
    gemmF(xh, xl, XCW, hh, hl, CW, nullptr, 0, MROW, CW, XCW, 0,
          nullptr, nullptr, 0, 0, 1, 0, out, XC_);

    // ---- serial z-chain (mode 2): y += into out, z planes from XC accum ----
    kzplanes<<<L1D(BB*ZP)>>>(z0h, z0l);
    for (int c = 0; c < NCH; ++c) {
        const bf16* ah = (c & 1) ? z1h : z0h;
        const bf16* al = (c & 1) ? z1l : z0l;
        bf16* oh = (c & 1) ? z0h : z1h;
        bf16* ol = (c & 1) ? z0l : z1l;
        gemmF(ah, al, ZP, Wh_, Wl_, CW, nullptr, 0, BB, CW, ZP, 0,
              oh, ol, ZP, YW, 2, c, out, XC_);
    }
}